// round 12
// baseline (speedup 1.0000x reference)
#include <cuda_runtime.h>
#include <cuda_bf16.h>
#include <math.h>
#include <limits.h>
#include <stdint.h>

#define NNODES 16384
#define NGRAPH 256
#define NODES_PER_G 64
#define HEADS 8
#define FDIM 64
#define HF 512
#define MAXE 262144

// ---------------- scratch (device globals; no allocations allowed) -------------
__device__ float g_xl[NNODES * HF];
__device__ float g_xr[NNODES * HF];
__device__ float g_go[NNODES * HF];
__device__ __nv_bfloat16 g_A2[(size_t)NNODES * 1024];  // [Ahi | Alo]  (2K, K<=512)
__device__ __nv_bfloat16 g_B2[(size_t)1024 * 1024];    // [Bhi | Blo]  (N-major)
__device__ int g_deg[NNODES];
__device__ int g_off[NNODES + 1];
__device__ int g_cur[NNODES];
__device__ int g_csr[MAXE];

// ---------------- helpers --------------------------------------------------------
__device__ __forceinline__ uint32_t smem_u32(const void* p) {
    uint32_t a;
    asm("{ .reg .u64 t; cvta.to.shared.u64 t, %1; cvt.u32.u64 %0, t; }" : "=r"(a) : "l"(p));
    return a;
}
__device__ __forceinline__ void cp16(void* dst, const void* src) {
    uint32_t d = smem_u32(dst);
    asm volatile("cp.async.cg.shared.global [%0], [%1], 16;" :: "r"(d), "l"(src));
}
__device__ __forceinline__ void ldsm4(uint32_t& r0, uint32_t& r1, uint32_t& r2,
                                      uint32_t& r3, uint32_t addr) {
    asm volatile("ldmatrix.sync.aligned.m8n8.x4.shared.b16 {%0,%1,%2,%3}, [%4];"
                 : "=r"(r0), "=r"(r1), "=r"(r2), "=r"(r3) : "r"(addr));
}
__device__ __forceinline__ void mma16816(float* c, uint32_t a0, uint32_t a1,
                                         uint32_t a2, uint32_t a3,
                                         uint32_t b0, uint32_t b1) {
    asm volatile(
        "mma.sync.aligned.m16n8k16.row.col.f32.bf16.bf16.f32 "
        "{%0,%1,%2,%3}, {%4,%5,%6,%7}, {%8,%9}, {%0,%1,%2,%3};"
        : "+f"(c[0]), "+f"(c[1]), "+f"(c[2]), "+f"(c[3])
        : "r"(a0), "r"(a1), "r"(a2), "r"(a3), "r"(b0), "r"(b1));
}

// ---------------- CSR build (graph topology; once per launch) --------------------
__global__ void hist_kernel(const int* __restrict__ dst, int E, int* __restrict__ deg) {
    int i = blockIdx.x * 256 + threadIdx.x;
    if (i < E) atomicAdd(&deg[dst[i]], 1);
}

__global__ __launch_bounds__(1024) void scan_kernel(const int* __restrict__ deg,
                                                    int* __restrict__ off,
                                                    int* __restrict__ cur) {
    __shared__ int sa[1024], sb[1024];
    int t = threadIdx.x;
    int base = t * 16;
    int local[16];
    int s = 0;
#pragma unroll
    for (int i = 0; i < 16; i++) { local[i] = s; s += deg[base + i]; }
    sa[t] = s;
    __syncthreads();
    int* pin = sa; int* pout = sb;
#pragma unroll
    for (int step = 1; step < 1024; step <<= 1) {
        int v = pin[t] + ((t >= step) ? pin[t - step] : 0);
        __syncthreads();
        pout[t] = v;
        __syncthreads();
        int* tmp = pin; pin = pout; pout = tmp;
    }
    int inc = pin[t];
    int exc = inc - s;
#pragma unroll
    for (int i = 0; i < 16; i++) {
        int o = exc + local[i];
        off[base + i] = o;
        cur[base + i] = o;
    }
    if (t == 1023) off[NNODES] = inc;
}

__global__ void scatter_kernel(const int* __restrict__ src, const int* __restrict__ dst,
                               int E, int* __restrict__ cur, int* __restrict__ csr) {
    int i = blockIdx.x * 256 + threadIdx.x;
    if (i >= E) return;
    int pos = atomicAdd(&cur[dst[i]], 1);
    csr[pos] = src[i];
}

// ---------------- weight prep: B2[n][hi|lo] from Wl/Wr --------------------------
__global__ void prep_w_kernel(const float* __restrict__ Wl,
                              const float* __restrict__ Wr,
                              __nv_bfloat16* __restrict__ B2, int K) {
    __shared__ float t[32][33];
    int k0 = blockIdx.x * 32, n0 = blockIdx.y * 32;
    int tx = threadIdx.x, ty = threadIdx.y;
    const float* W = (n0 < 512) ? Wl : Wr;
    int nn0 = n0 & 511;
    for (int i = ty; i < 32; i += 8)
        t[i][tx] = W[(size_t)(k0 + i) * 512 + nn0 + tx];
    __syncthreads();
    int K2 = 2 * K;
    for (int i = ty; i < 32; i += 8) {
        float v = t[tx][i];
        __nv_bfloat16 h = __float2bfloat16(v);
        __nv_bfloat16 l = __float2bfloat16(v - __bfloat162float(h));
        size_t base = (size_t)(n0 + i) * K2 + k0 + tx;
        B2[base]     = h;   // seg0: hi
        B2[base + K] = l;   // seg1: lo
    }
}

// ---------------- activation prep (layer 1 input only) --------------------------
__global__ void prep_a_kernel(const float* __restrict__ A,
                              __nv_bfloat16* __restrict__ A2, int K) {
    int i = blockIdx.x * 256 + threadIdx.x;
    if (i >= NNODES * K) return;
    int n = i / K, k = i - n * K;
    float v = A[i];
    __nv_bfloat16 h = __float2bfloat16(v);
    __nv_bfloat16 l = __float2bfloat16(v - __bfloat162float(h));
    size_t base = (size_t)n * (2 * K) + k;
    A2[base]     = h;   // hi
    A2[base + K] = l;   // lo
}

// ---------------- mma.sync bf16 GEMM, fused hi/lo, 256x128 CTA tile -------------
// C = Ahi*Bhi + Ahi*Blo + Alo*Bhi (fp32 accum)
// CTA 256(m) x 128(n), 16 warps (4M x 4N) of 64x32 (m16n8k16), BK=32,
// 2-stage double buffer, 1 CTA/SM.
#define BKB 32
#define LDS_AB 40                      // 32 + 8 skew
#define AROWS 256
#define BROWS 128
#define ST_A (AROWS * LDS_AB)          // 10240 elems
#define ST_B (BROWS * LDS_AB)          // 5120 elems
#define STG_E (2 * ST_A + 2 * ST_B)    // 30720 elems per stage
#define GEMM_SMEM (2 * STG_E * 2)      // 122880 bytes

__global__ __launch_bounds__(512, 1)
void gemm_bf16_kernel(const __nv_bfloat16* __restrict__ A2,
                      const __nv_bfloat16* __restrict__ B2,
                      float* __restrict__ Cl, float* __restrict__ Cr, int K)
{
    extern __shared__ __nv_bfloat16 sm[];

    const int tid = threadIdx.x;
    const int wid = tid >> 5;
    const int lane = tid & 31;
    const int m0 = blockIdx.y * 256;
    const int n0 = blockIdx.x * 128;
    const int wm = wid & 3;        // 0..3, 64-row slab
    const int wn = wid >> 2;       // 0..3, 32-col slab
    const int K2 = 2 * K;

    const __nv_bfloat16* Ab = A2 + (size_t)m0 * K2;
    const __nv_bfloat16* Bb = B2 + (size_t)n0 * K2;

    // cp.async geometry: A tiles 256 rows (row = tid/2, half = tid&1);
    // B tiles 128 rows, threads 0..255 -> Bh, 256..511 -> Bl
    const int arow = tid >> 1;
    const int ac = (tid & 1) * 16;
    const int btid = (tid < 256) ? tid : (tid - 256);
    const int brow = btid >> 1;
    const int bc = (btid & 1) * 16;
    const int bsel = (tid < 256) ? 0 : 1;   // 0 = Bhi tile, 1 = Blo tile

    // ldmatrix lane geometry (verified)
    const int aRow = wm * 64 + (lane & 15);
    const int aCol = (lane >> 4) * 8;
    const int bRow = (lane & 7) + (lane >> 4) * 8;
    const int bCol = ((lane >> 3) & 1) * 8;

    const uint32_t smBase = smem_u32(sm);

    float c[4][4][4];
#pragma unroll
    for (int g = 0; g < 4; g++)
#pragma unroll
        for (int h = 0; h < 4; h++)
#pragma unroll
            for (int r = 0; r < 4; r++) c[g][h][r] = 0.f;

    const int nk = K >> 5;

    // loader: chunk k0 -> stage st
    auto load_chunk = [&](int k0, int st) {
        __nv_bfloat16* S = sm + st * STG_E;
        // A hi
        {
            __nv_bfloat16* d = S + arow * LDS_AB + ac;
            const __nv_bfloat16* g0 = Ab + (size_t)arow * K2 + k0 + ac;
            cp16(d, g0); cp16(d + 8, g0 + 8);
        }
        // A lo
        {
            __nv_bfloat16* d = S + ST_A + arow * LDS_AB + ac;
            const __nv_bfloat16* g0 = Ab + (size_t)arow * K2 + K + k0 + ac;
            cp16(d, g0); cp16(d + 8, g0 + 8);
        }
        // B hi or lo
        {
            __nv_bfloat16* d = S + 2 * ST_A + bsel * ST_B + brow * LDS_AB + bc;
            const __nv_bfloat16* g0 = Bb + (size_t)brow * K2 + bsel * K + k0 + bc;
            cp16(d, g0); cp16(d + 8, g0 + 8);
        }
    };

    // prologue
    load_chunk(0, 0);
    asm volatile("cp.async.commit_group;");

    for (int kt = 0; kt < nk; kt++) {
        const int buf = kt & 1;
        asm volatile("cp.async.wait_group 0;");
        __syncthreads();

        if (kt + 1 < nk) load_chunk((kt + 1) * BKB, buf ^ 1);
        asm volatile("cp.async.commit_group;");

        const uint32_t stB = smBase + (buf * STG_E) * 2;
        const uint32_t aHiB = stB;
        const uint32_t aLoB = stB + ST_A * 2;
        const uint32_t bHiB = stB + 2 * ST_A * 2;
        const uint32_t bLoB = bHiB + ST_B * 2;

#pragma unroll
        for (int ks = 0; ks < 2; ks++) {
            uint32_t a[4][4];
#pragma unroll
            for (int g = 0; g < 4; g++)
                ldsm4(a[g][0], a[g][1], a[g][2], a[g][3],
                      aHiB + ((aRow + g * 16) * LDS_AB + ks * 16 + aCol) * 2);
            uint32_t bh[4][2];
#pragma unroll
            for (int h2 = 0; h2 < 2; h2++)
                ldsm4(bh[h2 * 2][0], bh[h2 * 2][1], bh[h2 * 2 + 1][0], bh[h2 * 2 + 1][1],
                      bHiB + ((wn * 32 + h2 * 16 + bRow) * LDS_AB + ks * 16 + bCol) * 2);
#pragma unroll
            for (int g = 0; g < 4; g++)
#pragma unroll
                for (int h = 0; h < 4; h++)
                    mma16816(c[g][h], a[g][0], a[g][1], a[g][2], a[g][3],
                             bh[h][0], bh[h][1]);

            uint32_t bl[4][2];
#pragma unroll
            for (int h2 = 0; h2 < 2; h2++)
                ldsm4(bl[h2 * 2][0], bl[h2 * 2][1], bl[h2 * 2 + 1][0], bl[h2 * 2 + 1][1],
                      bLoB + ((wn * 32 + h2 * 16 + bRow) * LDS_AB + ks * 16 + bCol) * 2);
#pragma unroll
            for (int g = 0; g < 4; g++)
#pragma unroll
                for (int h = 0; h < 4; h++)
                    mma16816(c[g][h], a[g][0], a[g][1], a[g][2], a[g][3],
                             bl[h][0], bl[h][1]);

            uint32_t al[4][4];
#pragma unroll
            for (int g = 0; g < 4; g++)
                ldsm4(al[g][0], al[g][1], al[g][2], al[g][3],
                      aLoB + ((aRow + g * 16) * LDS_AB + ks * 16 + aCol) * 2);
#pragma unroll
            for (int g = 0; g < 4; g++)
#pragma unroll
                for (int h = 0; h < 4; h++)
                    mma16816(c[g][h], al[g][0], al[g][1], al[g][2], al[g][3],
                             bh[h][0], bh[h][1]);
        }
    }
    asm volatile("cp.async.wait_group 0;");

    // epilogue
    float* Cbase = (n0 < 512) ? Cl : Cr;
    const int ncol = n0 & 511;
    const int crow = m0 + wm * 64 + (lane >> 2);
    const int ccol = ncol + wn * 32 + (lane & 3) * 2;
#pragma unroll
    for (int g = 0; g < 4; g++) {
#pragma unroll
        for (int h = 0; h < 4; h++) {
            float* p0 = Cbase + (size_t)(crow + g * 16) * HF + ccol + h * 8;
            *(float2*)p0 = make_float2(c[g][h][0], c[g][h][1]);
            float* p1 = p0 + 8 * HF;
            *(float2*)p1 = make_float2(c[g][h][2], c[g][h][3]);
        }
    }
}

// ---------------- fused CSR GAT (dual-edge unrolled), no atomics ----------------
__device__ __forceinline__ float warp_logit_reduce(float r) {
    r += __shfl_xor_sync(0xffffffffu, r, 8);
    r += __shfl_xor_sync(0xffffffffu, r, 4);
    r += __shfl_xor_sync(0xffffffffu, r, 2);
    r += __shfl_xor_sync(0xffffffffu, r, 1);
    return r;
}
__device__ __forceinline__ float leaky_dot(float4 a, float4 b, float4 t) {
    float mx = a.x + b.x, my = a.y + b.y, mz = a.z + b.z, mw = a.w + b.w;
    mx = mx > 0.f ? mx : 0.2f * mx;
    my = my > 0.f ? my : 0.2f * my;
    mz = mz > 0.f ? mz : 0.2f * mz;
    mw = mw > 0.f ? mw : 0.2f * mw;
    return mx * t.x + my * t.y + mz * t.z + mw * t.w;
}

__global__ __launch_bounds__(256) void gat_csr_concat_kernel(
    const int* __restrict__ off, const int* __restrict__ csr,
    const float* __restrict__ xl, const float* __restrict__ xr,
    const float* __restrict__ att, float* __restrict__ out)
{
    int d = blockIdx.x * 8 + (threadIdx.x >> 5);
    int lane = threadIdx.x & 31;
    const float4* at4 = (const float4*)att;
    const float4* pxr = (const float4*)(xr + (size_t)d * HF);
    float4 t[4], b[4], acc[4];
    float den[4];
#pragma unroll
    for (int it = 0; it < 4; it++) {
        t[it] = at4[it * 32 + lane];
        b[it] = pxr[it * 32 + lane];
        acc[it] = make_float4(0.f, 0.f, 0.f, 0.f);
        den[it] = 0.f;
    }
    int e0 = off[d], e1 = off[d + 1];
    int j = e0;
    for (; j + 1 < e1; j += 2) {
        int s0 = csr[j], s1 = csr[j + 1];
        const float4* p0 = (const float4*)(xl + (size_t)s0 * HF);
        const float4* p1 = (const float4*)(xl + (size_t)s1 * HF);
#pragma unroll
        for (int it = 0; it < 4; it++) {
            float4 a0 = p0[it * 32 + lane];
            float4 a1 = p1[it * 32 + lane];
            float r0 = warp_logit_reduce(leaky_dot(a0, b[it], t[it]));
            float r1 = warp_logit_reduce(leaky_dot(a1, b[it], t[it]));
            float pp0 = expf(r0);     // shift-free softmax (logits O(1))
            float pp1 = expf(r1);
            den[it] += pp0 + pp1;
            acc[it].x += pp0 * a0.x + pp1 * a1.x;
            acc[it].y += pp0 * a0.y + pp1 * a1.y;
            acc[it].z += pp0 * a0.z + pp1 * a1.z;
            acc[it].w += pp0 * a0.w + pp1 * a1.w;
        }
    }
    if (j < e1) {
        int s0 = csr[j];
        const float4* p0 = (const float4*)(xl + (size_t)s0 * HF);
#pragma unroll
        for (int it = 0; it < 4; it++) {
            float4 a0 = p0[it * 32 + lane];
            float r0 = warp_logit_reduce(leaky_dot(a0, b[it], t[it]));
            float pp0 = expf(r0);
            den[it] += pp0;
            acc[it].x += pp0 * a0.x; acc[it].y += pp0 * a0.y;
            acc[it].z += pp0 * a0.z; acc[it].w += pp0 * a0.w;
        }
    }
    float4* po = (float4*)(out + (size_t)d * HF);
#pragma unroll
    for (int it = 0; it < 4; it++) {
        float inv = 1.0f / (den[it] + 1e-16f);
        po[it * 32 + lane] = make_float4(acc[it].x * inv, acc[it].y * inv,
                                         acc[it].z * inv, acc[it].w * inv);
    }
}

__global__ __launch_bounds__(256) void gat_csr_mean_kernel(
    const int* __restrict__ off, const int* __restrict__ csr,
    const float* __restrict__ xl, const float* __restrict__ xr,
    const float* __restrict__ att, float* __restrict__ out)
{
    int d = blockIdx.x * 8 + (threadIdx.x >> 5);
    int lane = threadIdx.x & 31;
    const float4* at4 = (const float4*)att;
    const float4* pxr = (const float4*)(xr + (size_t)d * HF);
    float4 t[4], b[4], acc[4];
    float den[4];
#pragma unroll
    for (int it = 0; it < 4; it++) {
        t[it] = at4[it * 32 + lane];
        b[it] = pxr[it * 32 + lane];
        acc[it] = make_float4(0.f, 0.f, 0.f, 0.f);
        den[it] = 0.f;
    }
    int e0 = off[d], e1 = off[d + 1];
    int j = e0;
    for (; j + 1 < e1; j += 2) {
        int s0 = csr[j], s1 = csr[j + 1];
        const float4* p0 = (const float4*)(xl + (size_t)s0 * HF);
        const float4* p1 = (const float4*)(xl + (size_t)s1 * HF);
#pragma unroll
        for (int it = 0; it < 4; it++) {
            float4 a0 = p0[it * 32 + lane];
            float4 a1 = p1[it * 32 + lane];
            float r0 = warp_logit_reduce(leaky_dot(a0, b[it], t[it]));
            float r1 = warp_logit_reduce(leaky_dot(a1, b[it], t[it]));
            float pp0 = expf(r0);
            float pp1 = expf(r1);
            den[it] += pp0 + pp1;
            acc[it].x += pp0 * a0.x + pp1 * a1.x;
            acc[it].y += pp0 * a0.y + pp1 * a1.y;
            acc[it].z += pp0 * a0.z + pp1 * a1.z;
            acc[it].w += pp0 * a0.w + pp1 * a1.w;
        }
    }
    if (j < e1) {
        int s0 = csr[j];
        const float4* p0 = (const float4*)(xl + (size_t)s0 * HF);
#pragma unroll
        for (int it = 0; it < 4; it++) {
            float4 a0 = p0[it * 32 + lane];
            float r0 = warp_logit_reduce(leaky_dot(a0, b[it], t[it]));
            float pp0 = expf(r0);
            den[it] += pp0;
            acc[it].x += pp0 * a0.x; acc[it].y += pp0 * a0.y;
            acc[it].z += pp0 * a0.z; acc[it].w += pp0 * a0.w;
        }
    }
#pragma unroll
    for (int it = 0; it < 4; it++) {
        float inv = 1.0f / (den[it] + 1e-16f);
        acc[it].x *= inv; acc[it].y *= inv; acc[it].z *= inv; acc[it].w *= inv;
        acc[it].x += __shfl_xor_sync(0xffffffffu, acc[it].x, 16);
        acc[it].y += __shfl_xor_sync(0xffffffffu, acc[it].y, 16);
        acc[it].z += __shfl_xor_sync(0xffffffffu, acc[it].z, 16);
        acc[it].w += __shfl_xor_sync(0xffffffffu, acc[it].w, 16);
    }
    float4 tot;
    tot.x = (acc[0].x + acc[1].x + acc[2].x + acc[3].x) * 0.125f;
    tot.y = (acc[0].y + acc[1].y + acc[2].y + acc[3].y) * 0.125f;
    tot.z = (acc[0].z + acc[1].z + acc[2].z + acc[3].z) * 0.125f;
    tot.w = (acc[0].w + acc[1].w + acc[2].w + acc[3].w) * 0.125f;
    if (lane < 16)
        ((float4*)(out + (size_t)d * FDIM))[lane] = tot;
}

// ---------------- GraphNorm + bias + ReLU -> bf16 hi/lo split (layers 1,2) ------
__global__ __launch_bounds__(512) void graphnorm_relu_split_kernel(
    const float* __restrict__ gin, const float* __restrict__ bias,
    const float* __restrict__ w, const float* __restrict__ bb,
    const float* __restrict__ ms, __nv_bfloat16* __restrict__ A2)
{
    const int D = HF;              // 512
    int g = blockIdx.x;
    int c = threadIdx.x;
    const float* base = gin + (size_t)g * NODES_PER_G * D;
    float bc = bias[c];
    float s = 0.f;
#pragma unroll 8
    for (int i = 0; i < NODES_PER_G; i++) s += base[(size_t)i * D + c];
    float mean = (s + (float)NODES_PER_G * bc) * (1.0f / NODES_PER_G);
    float msm = ms[c] * mean;
    float var = 0.f;
#pragma unroll 8
    for (int i = 0; i < NODES_PER_G; i++) {
        float xc = base[(size_t)i * D + c] + bc - msm;
        var += xc * xc;
    }
    var *= (1.0f / NODES_PER_G);
    float inv = rsqrtf(var + 1e-5f);
    float wc = w[c], b2 = bb[c];
#pragma unroll 8
    for (int i = 0; i < NODES_PER_G; i++) {
        float xc = base[(size_t)i * D + c] + bc - msm;
        float y = wc * xc * inv + b2;
        y = y > 0.f ? y : 0.f;
        __nv_bfloat16 h = __float2bfloat16(y);
        __nv_bfloat16 l = __float2bfloat16(y - __bfloat162float(h));
        size_t a0 = (size_t)(g * NODES_PER_G + i) * 1024 + c;
        A2[a0]       = h;   // hi
        A2[a0 + 512] = l;   // lo
    }
}

// ---------------- GraphNorm L3 + ReLU + mean pool + linear head (fused) ---------
__global__ __launch_bounds__(64) void graphnorm_pool_linear_kernel(
    const float* __restrict__ gin, const float* __restrict__ bias,
    const float* __restrict__ w, const float* __restrict__ bb,
    const float* __restrict__ ms,
    const float* __restrict__ Wlin, const float* __restrict__ blin,
    float* __restrict__ out)
{
    const int D = FDIM;            // 64
    int g = blockIdx.x;
    int c = threadIdx.x;
    const float* base = gin + (size_t)g * NODES_PER_G * D;
    float bc = bias[c];
    float s = 0.f;
#pragma unroll 8
    for (int i = 0; i < NODES_PER_G; i++) s += base[(size_t)i * D + c];
    float mean = (s + (float)NODES_PER_G * bc) * (1.0f / NODES_PER_G);
    float msm = ms[c] * mean;
    float var = 0.f;
#pragma unroll 8
    for (int i = 0; i < NODES_PER_G; i++) {
        float xc = base[(size_t)i * D + c] + bc - msm;
        var += xc * xc;
    }
    var *= (1.0f / NODES_PER_G);
    float inv = rsqrtf(var + 1e-5f);
    float wc = w[c], b2 = bb[c];
    float psum = 0.f;
#pragma unroll 8
    for (int i = 0; i < NODES_PER_G; i++) {
        float xc = base[(size_t)i * D + c] + bc - msm;
        float y = wc * xc * inv + b2;
        psum += (y > 0.f ? y : 0.f);
    }
    __shared__ float pooled[FDIM];
    pooled[c] = psum * (1.0f / NODES_PER_G);
    __syncthreads();
    if (c < 2) {
        float acc = blin[c];
#pragma unroll
        for (int k = 0; k < FDIM; k++) acc += pooled[k] * Wlin[k * 2 + c];
        out[g * 2 + c] = acc;
    }
}

// ---------------- host side ------------------------------------------------------
extern "C" void kernel_launch(void* const* d_in, const int* in_sizes, int n_in,
                              void* d_out, int out_size)
{
    const float* x   = (const float*)d_in[0];
    const int*   src = (const int*)d_in[1];
    const int*   dst = (const int*)d_in[2];
    int E = in_sizes[1];

    const float* Wl1 = (const float*)d_in[4];
    const float* Wr1 = (const float*)d_in[5];
    const float* att1= (const float*)d_in[6];
    const float* b1  = (const float*)d_in[7];
    const float* gw1 = (const float*)d_in[8];
    const float* gb1 = (const float*)d_in[9];
    const float* gm1 = (const float*)d_in[10];

    const float* Wl2 = (const float*)d_in[11];
    const float* Wr2 = (const float*)d_in[12];
    const float* att2= (const float*)d_in[13];
    const float* b2  = (const float*)d_in[14];
    const float* gw2 = (const float*)d_in[15];
    const float* gb2 = (const float*)d_in[16];
    const float* gm2 = (const float*)d_in[17];

    const float* Wl3 = (const float*)d_in[18];
    const float* Wr3 = (const float*)d_in[19];
    const float* att3= (const float*)d_in[20];
    const float* b3  = (const float*)d_in[21];
    const float* gw3 = (const float*)d_in[22];
    const float* gb3 = (const float*)d_in[23];
    const float* gm3 = (const float*)d_in[24];

    const float* Wlin = (const float*)d_in[25];
    const float* blin = (const float*)d_in[26];

    float* out = (float*)d_out;

    cudaFuncSetAttribute(gemm_bf16_kernel,
                         cudaFuncAttributeMaxDynamicSharedMemorySize, GEMM_SMEM);

    float *xl, *xr, *go;
    __nv_bfloat16 *A2, *B2;
    int *deg, *off, *cur, *csr;
    cudaGetSymbolAddress((void**)&xl,  g_xl);
    cudaGetSymbolAddress((void**)&xr,  g_xr);
    cudaGetSymbolAddress((void**)&go,  g_go);
    cudaGetSymbolAddress((void**)&A2,  g_A2);
    cudaGetSymbolAddress((void**)&B2,  g_B2);
    cudaGetSymbolAddress((void**)&deg, g_deg);
    cudaGetSymbolAddress((void**)&off, g_off);
    cudaGetSymbolAddress((void**)&cur, g_cur);
    cudaGetSymbolAddress((void**)&csr, g_csr);

    // CSR build (once; shared by all 3 layers)
    cudaMemsetAsync(deg, 0, NNODES * sizeof(int));
    hist_kernel<<<(E + 255) / 256, 256>>>(dst, E, deg);
    scan_kernel<<<1, 1024>>>(deg, off, cur);
    scatter_kernel<<<(E + 255) / 256, 256>>>(src, dst, E, cur, csr);

    // ---- layer 1 (K=256) ----
    prep_a_kernel<<<(NNODES * 256 + 255) / 256, 256>>>(x, A2, 256);
    prep_w_kernel<<<dim3(8, 32), dim3(32, 8)>>>(Wl1, Wr1, B2, 256);
    gemm_bf16_kernel<<<dim3(8, 64), 512, GEMM_SMEM>>>(A2, B2, xl, xr, 256);
    gat_csr_concat_kernel<<<NNODES / 8, 256>>>(off, csr, xl, xr, att1, go);
    graphnorm_relu_split_kernel<<<NGRAPH, HF>>>(go, b1, gw1, gb1, gm1, A2);

    // ---- layer 2 (K=512) ----
    prep_w_kernel<<<dim3(16, 32), dim3(32, 8)>>>(Wl2, Wr2, B2, 512);
    gemm_bf16_kernel<<<dim3(8, 64), 512, GEMM_SMEM>>>(A2, B2, xl, xr, 512);
    gat_csr_concat_kernel<<<NNODES / 8, 256>>>(off, csr, xl, xr, att2, go);
    graphnorm_relu_split_kernel<<<NGRAPH, HF>>>(go, b2, gw2, gb2, gm2, A2);

    // ---- layer 3 (K=512, mean heads) + fused norm/pool/linear ----
    prep_w_kernel<<<dim3(16, 32), dim3(32, 8)>>>(Wl3, Wr3, B2, 512);
    gemm_bf16_kernel<<<dim3(8, 64), 512, GEMM_SMEM>>>(A2, B2, xl, xr, 512);
    gat_csr_mean_kernel<<<NNODES / 8, 256>>>(off, csr, xl, xr, att3, go);
    graphnorm_pool_linear_kernel<<<NGRAPH, FDIM>>>(go, b3, gw3, gb3, gm3,
                                                   Wlin, blin, out);
}

// round 13
// speedup vs baseline: 1.0318x; 1.0318x over previous
#include <cuda_runtime.h>
#include <cuda_bf16.h>
#include <math.h>
#include <limits.h>
#include <stdint.h>

#define NNODES 16384
#define NGRAPH 256
#define NODES_PER_G 64
#define HEADS 8
#define FDIM 64
#define HF 512
#define MAXE 262144

// ---------------- scratch (device globals; no allocations allowed) -------------
__device__ float g_xl[NNODES * HF];
__device__ float g_xr[NNODES * HF];
__device__ float g_go[NNODES * HF];
__device__ __nv_bfloat16 g_A2[(size_t)NNODES * 1024];  // [Ahi | Alo]  (2K, K<=512)
__device__ __nv_bfloat16 g_B2[(size_t)1024 * 1024];    // [Bhi | Blo]  (N-major)
__device__ int g_deg[NNODES];
__device__ int g_off[NNODES + 1];
__device__ int g_cur[NNODES];
__device__ int g_csr[MAXE];

// ---------------- helpers --------------------------------------------------------
__device__ __forceinline__ uint32_t smem_u32(const void* p) {
    uint32_t a;
    asm("{ .reg .u64 t; cvta.to.shared.u64 t, %1; cvt.u32.u64 %0, t; }" : "=r"(a) : "l"(p));
    return a;
}
__device__ __forceinline__ void cp16(void* dst, const void* src) {
    uint32_t d = smem_u32(dst);
    asm volatile("cp.async.cg.shared.global [%0], [%1], 16;" :: "r"(d), "l"(src));
}
__device__ __forceinline__ void ldsm4(uint32_t& r0, uint32_t& r1, uint32_t& r2,
                                      uint32_t& r3, uint32_t addr) {
    asm volatile("ldmatrix.sync.aligned.m8n8.x4.shared.b16 {%0,%1,%2,%3}, [%4];"
                 : "=r"(r0), "=r"(r1), "=r"(r2), "=r"(r3) : "r"(addr));
}
__device__ __forceinline__ void mma16816(float* c, uint32_t a0, uint32_t a1,
                                         uint32_t a2, uint32_t a3,
                                         uint32_t b0, uint32_t b1) {
    asm volatile(
        "mma.sync.aligned.m16n8k16.row.col.f32.bf16.bf16.f32 "
        "{%0,%1,%2,%3}, {%4,%5,%6,%7}, {%8,%9}, {%0,%1,%2,%3};"
        : "+f"(c[0]), "+f"(c[1]), "+f"(c[2]), "+f"(c[3])
        : "r"(a0), "r"(a1), "r"(a2), "r"(a3), "r"(b0), "r"(b1));
}

// ---------------- CSR build (graph topology; once per launch) --------------------
__global__ void hist_kernel(const int* __restrict__ dst, int E, int* __restrict__ deg) {
    int i = blockIdx.x * 256 + threadIdx.x;
    if (i < E) atomicAdd(&deg[dst[i]], 1);
}

__global__ __launch_bounds__(1024) void scan_kernel(const int* __restrict__ deg,
                                                    int* __restrict__ off,
                                                    int* __restrict__ cur) {
    __shared__ int sa[1024], sb[1024];
    int t = threadIdx.x;
    int base = t * 16;
    int local[16];
    int s = 0;
#pragma unroll
    for (int i = 0; i < 16; i++) { local[i] = s; s += deg[base + i]; }
    sa[t] = s;
    __syncthreads();
    int* pin = sa; int* pout = sb;
#pragma unroll
    for (int step = 1; step < 1024; step <<= 1) {
        int v = pin[t] + ((t >= step) ? pin[t - step] : 0);
        __syncthreads();
        pout[t] = v;
        __syncthreads();
        int* tmp = pin; pin = pout; pout = tmp;
    }
    int inc = pin[t];
    int exc = inc - s;
#pragma unroll
    for (int i = 0; i < 16; i++) {
        int o = exc + local[i];
        off[base + i] = o;
        cur[base + i] = o;
    }
    if (t == 1023) off[NNODES] = inc;
}

__global__ void scatter_kernel(const int* __restrict__ src, const int* __restrict__ dst,
                               int E, int* __restrict__ cur, int* __restrict__ csr) {
    int i = blockIdx.x * 256 + threadIdx.x;
    if (i >= E) return;
    int pos = atomicAdd(&cur[dst[i]], 1);
    csr[pos] = src[i];
}

// ---------------- weight prep: B2[n][hi|lo] from Wl/Wr --------------------------
__global__ void prep_w_kernel(const float* __restrict__ Wl,
                              const float* __restrict__ Wr,
                              __nv_bfloat16* __restrict__ B2, int K) {
    __shared__ float t[32][33];
    int k0 = blockIdx.x * 32, n0 = blockIdx.y * 32;
    int tx = threadIdx.x, ty = threadIdx.y;
    const float* W = (n0 < 512) ? Wl : Wr;
    int nn0 = n0 & 511;
    for (int i = ty; i < 32; i += 8)
        t[i][tx] = W[(size_t)(k0 + i) * 512 + nn0 + tx];
    __syncthreads();
    int K2 = 2 * K;
    for (int i = ty; i < 32; i += 8) {
        float v = t[tx][i];
        __nv_bfloat16 h = __float2bfloat16(v);
        __nv_bfloat16 l = __float2bfloat16(v - __bfloat162float(h));
        size_t base = (size_t)(n0 + i) * K2 + k0 + tx;
        B2[base]     = h;   // seg0: hi
        B2[base + K] = l;   // seg1: lo
    }
}

// ---------------- activation prep (layer 1 input only) --------------------------
__global__ void prep_a_kernel(const float* __restrict__ A,
                              __nv_bfloat16* __restrict__ A2, int K) {
    int i = blockIdx.x * 256 + threadIdx.x;
    if (i >= NNODES * K) return;
    int n = i / K, k = i - n * K;
    float v = A[i];
    __nv_bfloat16 h = __float2bfloat16(v);
    __nv_bfloat16 l = __float2bfloat16(v - __bfloat162float(h));
    size_t base = (size_t)n * (2 * K) + k;
    A2[base]     = h;   // hi
    A2[base + K] = l;   // lo
}

// ---------------- mma.sync bf16 GEMM with hi/lo dedup (round-11 config) ---------
// C[16384,1024] = Ahi*Bhi + Ahi*Blo + Alo*Bhi  (fp32 accum)
// CTA tile 128(m) x 128(n), 8 warps (2M x 4N) of 64x32 (m16n8k16), BK=32,
// 3-stage cp.async, 2 CTAs/SM.  Loop1: Ahi vs (Bhi,Blo); Loop2: Alo vs Bhi.
#define BKB 32
#define LDS_AB 40                    // 32 + 8 skew
#define NST 3
#define ST_T (128 * LDS_AB)          // elems per tile per stage
#define GEMM_SMEM (NST * 3 * ST_T * 2)   // 92160 bytes

__global__ __launch_bounds__(256, 2)
void gemm_bf16_kernel(const __nv_bfloat16* __restrict__ A2,
                      const __nv_bfloat16* __restrict__ B2,
                      float* __restrict__ Cl, float* __restrict__ Cr, int K)
{
    extern __shared__ __nv_bfloat16 sm[];
    __nv_bfloat16* As = sm;                     // [NST][128][40]
    __nv_bfloat16* Bh = sm + NST * ST_T;        // [NST][128][40]
    __nv_bfloat16* Bl = sm + 2 * NST * ST_T;    // [NST][128][40]

    const int tid = threadIdx.x;
    const int wid = tid >> 5;
    const int lane = tid & 31;
    const int m0 = blockIdx.y * 128;
    const int n0 = blockIdx.x * 128;
    const int wm = wid & 1;        // 64-row slab
    const int wn = wid >> 1;       // 0..3, 32-col slab
    const int K2 = 2 * K;

    const __nv_bfloat16* Ab = A2 + (size_t)m0 * K2;
    const __nv_bfloat16* Bb = B2 + (size_t)n0 * K2;

    const int row = tid >> 1;
    const int c0 = (tid & 1) * 16;

    // ldmatrix lane geometry (verified)
    const int aRow = wm * 64 + (lane & 15);
    const int aCol = (lane >> 4) * 8;
    const int bRow = (lane & 7) + (lane >> 4) * 8;
    const int bCol = ((lane >> 3) & 1) * 8;

    const uint32_t sAs = smem_u32(As);
    const uint32_t sBh = smem_u32(Bh);
    const uint32_t sBl = smem_u32(Bl);

    float c[4][4][4];
#pragma unroll
    for (int g = 0; g < 4; g++)
#pragma unroll
        for (int h = 0; h < 4; h++)
#pragma unroll
            for (int r = 0; r < 4; r++) c[g][h][r] = 0.f;

    const int nk = K >> 5;   // chunks per pass

    // ================= LOOP 1: Ahi x (Bhi, Blo) =================
#pragma unroll
    for (int st = 0; st < NST - 1; st++) {
        const int k0 = st * BKB;
        __nv_bfloat16* as = As + st * ST_T + row * LDS_AB + c0;
        const __nv_bfloat16* ag = Ab + (size_t)row * K2 + k0 + c0;
        cp16(as, ag); cp16(as + 8, ag + 8);
        __nv_bfloat16* bh = Bh + st * ST_T + row * LDS_AB + c0;
        const __nv_bfloat16* bgh = Bb + (size_t)row * K2 + k0 + c0;
        cp16(bh, bgh); cp16(bh + 8, bgh + 8);
        __nv_bfloat16* bl = Bl + st * ST_T + row * LDS_AB + c0;
        const __nv_bfloat16* bgl = bgh + K;
        cp16(bl, bgl); cp16(bl + 8, bgl + 8);
        asm volatile("cp.async.commit_group;");
    }

    for (int kt = 0; kt < nk; kt++) {
        const int buf = kt % NST;
        asm volatile("cp.async.wait_group %0;" :: "n"(NST - 2));
        __syncthreads();

        const uint32_t aBase = sAs + (buf * ST_T) * 2;
        const uint32_t hBase = sBh + (buf * ST_T) * 2;
        const uint32_t lBase = sBl + (buf * ST_T) * 2;
#pragma unroll
        for (int ks = 0; ks < 2; ks++) {
            uint32_t a[4][4];
#pragma unroll
            for (int g = 0; g < 4; g++)
                ldsm4(a[g][0], a[g][1], a[g][2], a[g][3],
                      aBase + ((aRow + g * 16) * LDS_AB + ks * 16 + aCol) * 2);
            uint32_t bh[4][2], bl[4][2];
#pragma unroll
            for (int h2 = 0; h2 < 2; h2++) {
                ldsm4(bh[h2 * 2][0], bh[h2 * 2][1], bh[h2 * 2 + 1][0], bh[h2 * 2 + 1][1],
                      hBase + ((wn * 32 + h2 * 16 + bRow) * LDS_AB + ks * 16 + bCol) * 2);
                ldsm4(bl[h2 * 2][0], bl[h2 * 2][1], bl[h2 * 2 + 1][0], bl[h2 * 2 + 1][1],
                      lBase + ((wn * 32 + h2 * 16 + bRow) * LDS_AB + ks * 16 + bCol) * 2);
            }
#pragma unroll
            for (int g = 0; g < 4; g++)
#pragma unroll
                for (int h = 0; h < 4; h++) {
                    mma16816(c[g][h], a[g][0], a[g][1], a[g][2], a[g][3],
                             bh[h][0], bh[h][1]);
                    mma16816(c[g][h], a[g][0], a[g][1], a[g][2], a[g][3],
                             bl[h][0], bl[h][1]);
                }
        }

        const int knext = kt + NST - 1;
        if (knext < nk) {
            const int st = knext % NST;
            const int k0 = knext * BKB;
            __nv_bfloat16* as = As + st * ST_T + row * LDS_AB + c0;
            const __nv_bfloat16* ag = Ab + (size_t)row * K2 + k0 + c0;
            cp16(as, ag); cp16(as + 8, ag + 8);
            __nv_bfloat16* bh2 = Bh + st * ST_T + row * LDS_AB + c0;
            const __nv_bfloat16* bgh = Bb + (size_t)row * K2 + k0 + c0;
            cp16(bh2, bgh); cp16(bh2 + 8, bgh + 8);
            __nv_bfloat16* bl2 = Bl + st * ST_T + row * LDS_AB + c0;
            const __nv_bfloat16* bgl = bgh + K;
            cp16(bl2, bgl); cp16(bl2 + 8, bgl + 8);
        }
        asm volatile("cp.async.commit_group;");
    }

    // drain pipeline before reusing smem
    asm volatile("cp.async.wait_group 0;");
    __syncthreads();

    // ================= LOOP 2: Alo x Bhi =================
#pragma unroll
    for (int st = 0; st < NST - 1; st++) {
        const int k0 = st * BKB;
        __nv_bfloat16* as = As + st * ST_T + row * LDS_AB + c0;
        const __nv_bfloat16* ag = Ab + (size_t)row * K2 + K + k0 + c0;   // A lo
        cp16(as, ag); cp16(as + 8, ag + 8);
        __nv_bfloat16* bh = Bh + st * ST_T + row * LDS_AB + c0;
        const __nv_bfloat16* bgh = Bb + (size_t)row * K2 + k0 + c0;      // B hi
        cp16(bh, bgh); cp16(bh + 8, bgh + 8);
        asm volatile("cp.async.commit_group;");
    }

    for (int kt = 0; kt < nk; kt++) {
        const int buf = kt % NST;
        asm volatile("cp.async.wait_group %0;" :: "n"(NST - 2));
        __syncthreads();

        const uint32_t aBase = sAs + (buf * ST_T) * 2;
        const uint32_t hBase = sBh + (buf * ST_T) * 2;
#pragma unroll
        for (int ks = 0; ks < 2; ks++) {
            uint32_t a[4][4];
#pragma unroll
            for (int g = 0; g < 4; g++)
                ldsm4(a[g][0], a[g][1], a[g][2], a[g][3],
                      aBase + ((aRow + g * 16) * LDS_AB + ks * 16 + aCol) * 2);
            uint32_t bh[4][2];
#pragma unroll
            for (int h2 = 0; h2 < 2; h2++)
                ldsm4(bh[h2 * 2][0], bh[h2 * 2][1], bh[h2 * 2 + 1][0], bh[h2 * 2 + 1][1],
                      hBase + ((wn * 32 + h2 * 16 + bRow) * LDS_AB + ks * 16 + bCol) * 2);
#pragma unroll
            for (int g = 0; g < 4; g++)
#pragma unroll
                for (int h = 0; h < 4; h++)
                    mma16816(c[g][h], a[g][0], a[g][1], a[g][2], a[g][3],
                             bh[h][0], bh[h][1]);
        }

        const int knext = kt + NST - 1;
        if (knext < nk) {
            const int st = knext % NST;
            const int k0 = knext * BKB;
            __nv_bfloat16* as = As + st * ST_T + row * LDS_AB + c0;
            const __nv_bfloat16* ag = Ab + (size_t)row * K2 + K + k0 + c0;
            cp16(as, ag); cp16(as + 8, ag + 8);
            __nv_bfloat16* bh2 = Bh + st * ST_T + row * LDS_AB + c0;
            const __nv_bfloat16* bgh = Bb + (size_t)row * K2 + k0 + c0;
            cp16(bh2, bgh); cp16(bh2 + 8, bgh + 8);
        }
        asm volatile("cp.async.commit_group;");
    }
    asm volatile("cp.async.wait_group 0;");

    // epilogue
    float* Cbase = (n0 < 512) ? Cl : Cr;
    const int ncol = n0 & 511;
    const int crow = m0 + wm * 64 + (lane >> 2);
    const int ccol = ncol + wn * 32 + (lane & 3) * 2;
#pragma unroll
    for (int g = 0; g < 4; g++) {
#pragma unroll
        for (int h = 0; h < 4; h++) {
            float* p0 = Cbase + (size_t)(crow + g * 16) * HF + ccol + h * 8;
            *(float2*)p0 = make_float2(c[g][h][0], c[g][h][1]);
            float* p1 = p0 + 8 * HF;
            *(float2*)p1 = make_float2(c[g][h][2], c[g][h][3]);
        }
    }
}

// ---------------- fused CSR GAT (dual-edge unrolled), no atomics ----------------
__device__ __forceinline__ float warp_logit_reduce(float r) {
    r += __shfl_xor_sync(0xffffffffu, r, 8);
    r += __shfl_xor_sync(0xffffffffu, r, 4);
    r += __shfl_xor_sync(0xffffffffu, r, 2);
    r += __shfl_xor_sync(0xffffffffu, r, 1);
    return r;
}
__device__ __forceinline__ float leaky_dot(float4 a, float4 b, float4 t) {
    float mx = a.x + b.x, my = a.y + b.y, mz = a.z + b.z, mw = a.w + b.w;
    mx = mx > 0.f ? mx : 0.2f * mx;
    my = my > 0.f ? my : 0.2f * my;
    mz = mz > 0.f ? mz : 0.2f * mz;
    mw = mw > 0.f ? mw : 0.2f * mw;
    return mx * t.x + my * t.y + mz * t.z + mw * t.w;
}

__global__ __launch_bounds__(256) void gat_csr_concat_kernel(
    const int* __restrict__ off, const int* __restrict__ csr,
    const float* __restrict__ xl, const float* __restrict__ xr,
    const float* __restrict__ att, float* __restrict__ out)
{
    int d = blockIdx.x * 8 + (threadIdx.x >> 5);
    int lane = threadIdx.x & 31;
    const float4* at4 = (const float4*)att;
    const float4* pxr = (const float4*)(xr + (size_t)d * HF);
    float4 t[4], b[4], acc[4];
    float den[4];
#pragma unroll
    for (int it = 0; it < 4; it++) {
        t[it] = at4[it * 32 + lane];
        b[it] = pxr[it * 32 + lane];
        acc[it] = make_float4(0.f, 0.f, 0.f, 0.f);
        den[it] = 0.f;
    }
    int e0 = off[d], e1 = off[d + 1];
    int j = e0;
    for (; j + 1 < e1; j += 2) {
        int s0 = csr[j], s1 = csr[j + 1];
        const float4* p0 = (const float4*)(xl + (size_t)s0 * HF);
        const float4* p1 = (const float4*)(xl + (size_t)s1 * HF);
#pragma unroll
        for (int it = 0; it < 4; it++) {
            float4 a0 = p0[it * 32 + lane];
            float4 a1 = p1[it * 32 + lane];
            float r0 = warp_logit_reduce(leaky_dot(a0, b[it], t[it]));
            float r1 = warp_logit_reduce(leaky_dot(a1, b[it], t[it]));
            float pp0 = expf(r0);     // shift-free softmax (logits O(1))
            float pp1 = expf(r1);
            den[it] += pp0 + pp1;
            acc[it].x += pp0 * a0.x + pp1 * a1.x;
            acc[it].y += pp0 * a0.y + pp1 * a1.y;
            acc[it].z += pp0 * a0.z + pp1 * a1.z;
            acc[it].w += pp0 * a0.w + pp1 * a1.w;
        }
    }
    if (j < e1) {
        int s0 = csr[j];
        const float4* p0 = (const float4*)(xl + (size_t)s0 * HF);
#pragma unroll
        for (int it = 0; it < 4; it++) {
            float4 a0 = p0[it * 32 + lane];
            float r0 = warp_logit_reduce(leaky_dot(a0, b[it], t[it]));
            float pp0 = expf(r0);
            den[it] += pp0;
            acc[it].x += pp0 * a0.x; acc[it].y += pp0 * a0.y;
            acc[it].z += pp0 * a0.z; acc[it].w += pp0 * a0.w;
        }
    }
    float4* po = (float4*)(out + (size_t)d * HF);
#pragma unroll
    for (int it = 0; it < 4; it++) {
        float inv = 1.0f / (den[it] + 1e-16f);
        po[it * 32 + lane] = make_float4(acc[it].x * inv, acc[it].y * inv,
                                         acc[it].z * inv, acc[it].w * inv);
    }
}

__global__ __launch_bounds__(256) void gat_csr_mean_kernel(
    const int* __restrict__ off, const int* __restrict__ csr,
    const float* __restrict__ xl, const float* __restrict__ xr,
    const float* __restrict__ att, float* __restrict__ out)
{
    int d = blockIdx.x * 8 + (threadIdx.x >> 5);
    int lane = threadIdx.x & 31;
    const float4* at4 = (const float4*)att;
    const float4* pxr = (const float4*)(xr + (size_t)d * HF);
    float4 t[4], b[4], acc[4];
    float den[4];
#pragma unroll
    for (int it = 0; it < 4; it++) {
        t[it] = at4[it * 32 + lane];
        b[it] = pxr[it * 32 + lane];
        acc[it] = make_float4(0.f, 0.f, 0.f, 0.f);
        den[it] = 0.f;
    }
    int e0 = off[d], e1 = off[d + 1];
    int j = e0;
    for (; j + 1 < e1; j += 2) {
        int s0 = csr[j], s1 = csr[j + 1];
        const float4* p0 = (const float4*)(xl + (size_t)s0 * HF);
        const float4* p1 = (const float4*)(xl + (size_t)s1 * HF);
#pragma unroll
        for (int it = 0; it < 4; it++) {
            float4 a0 = p0[it * 32 + lane];
            float4 a1 = p1[it * 32 + lane];
            float r0 = warp_logit_reduce(leaky_dot(a0, b[it], t[it]));
            float r1 = warp_logit_reduce(leaky_dot(a1, b[it], t[it]));
            float pp0 = expf(r0);
            float pp1 = expf(r1);
            den[it] += pp0 + pp1;
            acc[it].x += pp0 * a0.x + pp1 * a1.x;
            acc[it].y += pp0 * a0.y + pp1 * a1.y;
            acc[it].z += pp0 * a0.z + pp1 * a1.z;
            acc[it].w += pp0 * a0.w + pp1 * a1.w;
        }
    }
    if (j < e1) {
        int s0 = csr[j];
        const float4* p0 = (const float4*)(xl + (size_t)s0 * HF);
#pragma unroll
        for (int it = 0; it < 4; it++) {
            float4 a0 = p0[it * 32 + lane];
            float r0 = warp_logit_reduce(leaky_dot(a0, b[it], t[it]));
            float pp0 = expf(r0);
            den[it] += pp0;
            acc[it].x += pp0 * a0.x; acc[it].y += pp0 * a0.y;
            acc[it].z += pp0 * a0.z; acc[it].w += pp0 * a0.w;
        }
    }
#pragma unroll
    for (int it = 0; it < 4; it++) {
        float inv = 1.0f / (den[it] + 1e-16f);
        acc[it].x *= inv; acc[it].y *= inv; acc[it].z *= inv; acc[it].w *= inv;
        acc[it].x += __shfl_xor_sync(0xffffffffu, acc[it].x, 16);
        acc[it].y += __shfl_xor_sync(0xffffffffu, acc[it].y, 16);
        acc[it].z += __shfl_xor_sync(0xffffffffu, acc[it].z, 16);
        acc[it].w += __shfl_xor_sync(0xffffffffu, acc[it].w, 16);
    }
    float4 tot;
    tot.x = (acc[0].x + acc[1].x + acc[2].x + acc[3].x) * 0.125f;
    tot.y = (acc[0].y + acc[1].y + acc[2].y + acc[3].y) * 0.125f;
    tot.z = (acc[0].z + acc[1].z + acc[2].z + acc[3].z) * 0.125f;
    tot.w = (acc[0].w + acc[1].w + acc[2].w + acc[3].w) * 0.125f;
    if (lane < 16)
        ((float4*)(out + (size_t)d * FDIM))[lane] = tot;
}

// ---------------- GraphNorm + bias + ReLU -> bf16 hi/lo split (layers 1,2) ------
__global__ __launch_bounds__(512) void graphnorm_relu_split_kernel(
    const float* __restrict__ gin, const float* __restrict__ bias,
    const float* __restrict__ w, const float* __restrict__ bb,
    const float* __restrict__ ms, __nv_bfloat16* __restrict__ A2)
{
    const int D = HF;              // 512
    int g = blockIdx.x;
    int c = threadIdx.x;
    const float* base = gin + (size_t)g * NODES_PER_G * D;
    float bc = bias[c];
    float s = 0.f;
#pragma unroll 8
    for (int i = 0; i < NODES_PER_G; i++) s += base[(size_t)i * D + c];
    float mean = (s + (float)NODES_PER_G * bc) * (1.0f / NODES_PER_G);
    float msm = ms[c] * mean;
    float var = 0.f;
#pragma unroll 8
    for (int i = 0; i < NODES_PER_G; i++) {
        float xc = base[(size_t)i * D + c] + bc - msm;
        var += xc * xc;
    }
    var *= (1.0f / NODES_PER_G);
    float inv = rsqrtf(var + 1e-5f);
    float wc = w[c], b2 = bb[c];
#pragma unroll 8
    for (int i = 0; i < NODES_PER_G; i++) {
        float xc = base[(size_t)i * D + c] + bc - msm;
        float y = wc * xc * inv + b2;
        y = y > 0.f ? y : 0.f;
        __nv_bfloat16 h = __float2bfloat16(y);
        __nv_bfloat16 l = __float2bfloat16(y - __bfloat162float(h));
        size_t a0 = (size_t)(g * NODES_PER_G + i) * 1024 + c;
        A2[a0]       = h;   // hi
        A2[a0 + 512] = l;   // lo
    }
}

// ---------------- GraphNorm L3 + ReLU + mean pool + linear head (fused) ---------
__global__ __launch_bounds__(64) void graphnorm_pool_linear_kernel(
    const float* __restrict__ gin, const float* __restrict__ bias,
    const float* __restrict__ w, const float* __restrict__ bb,
    const float* __restrict__ ms,
    const float* __restrict__ Wlin, const float* __restrict__ blin,
    float* __restrict__ out)
{
    const int D = FDIM;            // 64
    int g = blockIdx.x;
    int c = threadIdx.x;
    const float* base = gin + (size_t)g * NODES_PER_G * D;
    float bc = bias[c];
    float s = 0.f;
#pragma unroll 8
    for (int i = 0; i < NODES_PER_G; i++) s += base[(size_t)i * D + c];
    float mean = (s + (float)NODES_PER_G * bc) * (1.0f / NODES_PER_G);
    float msm = ms[c] * mean;
    float var = 0.f;
#pragma unroll 8
    for (int i = 0; i < NODES_PER_G; i++) {
        float xc = base[(size_t)i * D + c] + bc - msm;
        var += xc * xc;
    }
    var *= (1.0f / NODES_PER_G);
    float inv = rsqrtf(var + 1e-5f);
    float wc = w[c], b2 = bb[c];
    float psum = 0.f;
#pragma unroll 8
    for (int i = 0; i < NODES_PER_G; i++) {
        float xc = base[(size_t)i * D + c] + bc - msm;
        float y = wc * xc * inv + b2;
        psum += (y > 0.f ? y : 0.f);
    }
    __shared__ float pooled[FDIM];
    pooled[c] = psum * (1.0f / NODES_PER_G);
    __syncthreads();
    if (c < 2) {
        float acc = blin[c];
#pragma unroll
        for (int k = 0; k < FDIM; k++) acc += pooled[k] * Wlin[k * 2 + c];
        out[g * 2 + c] = acc;
    }
}

// ---------------- host side ------------------------------------------------------
extern "C" void kernel_launch(void* const* d_in, const int* in_sizes, int n_in,
                              void* d_out, int out_size)
{
    const float* x   = (const float*)d_in[0];
    const int*   src = (const int*)d_in[1];
    const int*   dst = (const int*)d_in[2];
    int E = in_sizes[1];

    const float* Wl1 = (const float*)d_in[4];
    const float* Wr1 = (const float*)d_in[5];
    const float* att1= (const float*)d_in[6];
    const float* b1  = (const float*)d_in[7];
    const float* gw1 = (const float*)d_in[8];
    const float* gb1 = (const float*)d_in[9];
    const float* gm1 = (const float*)d_in[10];

    const float* Wl2 = (const float*)d_in[11];
    const float* Wr2 = (const float*)d_in[12];
    const float* att2= (const float*)d_in[13];
    const float* b2  = (const float*)d_in[14];
    const float* gw2 = (const float*)d_in[15];
    const float* gb2 = (const float*)d_in[16];
    const float* gm2 = (const float*)d_in[17];

    const float* Wl3 = (const float*)d_in[18];
    const float* Wr3 = (const float*)d_in[19];
    const float* att3= (const float*)d_in[20];
    const float* b3  = (const float*)d_in[21];
    const float* gw3 = (const float*)d_in[22];
    const float* gb3 = (const float*)d_in[23];
    const float* gm3 = (const float*)d_in[24];

    const float* Wlin = (const float*)d_in[25];
    const float* blin = (const float*)d_in[26];

    float* out = (float*)d_out;

    cudaFuncSetAttribute(gemm_bf16_kernel,
                         cudaFuncAttributeMaxDynamicSharedMemorySize, GEMM_SMEM);

    float *xl, *xr, *go;
    __nv_bfloat16 *A2, *B2;
    int *deg, *off, *cur, *csr;
    cudaGetSymbolAddress((void**)&xl,  g_xl);
    cudaGetSymbolAddress((void**)&xr,  g_xr);
    cudaGetSymbolAddress((void**)&go,  g_go);
    cudaGetSymbolAddress((void**)&A2,  g_A2);
    cudaGetSymbolAddress((void**)&B2,  g_B2);
    cudaGetSymbolAddress((void**)&deg, g_deg);
    cudaGetSymbolAddress((void**)&off, g_off);
    cudaGetSymbolAddress((void**)&cur, g_cur);
    cudaGetSymbolAddress((void**)&csr, g_csr);

    // CSR build (once; shared by all 3 layers)
    cudaMemsetAsync(deg, 0, NNODES * sizeof(int));
    hist_kernel<<<(E + 255) / 256, 256>>>(dst, E, deg);
    scan_kernel<<<1, 1024>>>(deg, off, cur);
    scatter_kernel<<<(E + 255) / 256, 256>>>(src, dst, E, cur, csr);

    // ---- layer 1 (K=256) ----
    prep_a_kernel<<<(NNODES * 256 + 255) / 256, 256>>>(x, A2, 256);
    prep_w_kernel<<<dim3(8, 32), dim3(32, 8)>>>(Wl1, Wr1, B2, 256);
    gemm_bf16_kernel<<<dim3(8, 128), 256, GEMM_SMEM>>>(A2, B2, xl, xr, 256);
    gat_csr_concat_kernel<<<NNODES / 8, 256>>>(off, csr, xl, xr, att1, go);
    graphnorm_relu_split_kernel<<<NGRAPH, HF>>>(go, b1, gw1, gb1, gm1, A2);

    // ---- layer 2 (K=512) ----
    prep_w_kernel<<<dim3(16, 32), dim3(32, 8)>>>(Wl2, Wr2, B2, 512);
    gemm_bf16_kernel<<<dim3(8, 128), 256, GEMM_SMEM>>>(A2, B2, xl, xr, 512);
    gat_csr_concat_kernel<<<NNODES / 8, 256>>>(off, csr, xl, xr, att2, go);
    graphnorm_relu_split_kernel<<<NGRAPH, HF>>>(go, b2, gw2, gb2, gm2, A2);

    // ---- layer 3 (K=512, mean heads) + fused norm/pool/linear ----
    prep_w_kernel<<<dim3(16, 32), dim3(32, 8)>>>(Wl3, Wr3, B2, 512);
    gemm_bf16_kernel<<<dim3(8, 128), 256, GEMM_SMEM>>>(A2, B2, xl, xr, 512);
    gat_csr_mean_kernel<<<NNODES / 8, 256>>>(off, csr, xl, xr, att3, go);
    graphnorm_pool_linear_kernel<<<NGRAPH, FDIM>>>(go, b3, gw3, gb3, gm3,
                                                   Wlin, blin, out);
}

// round 15
// speedup vs baseline: 1.1103x; 1.0760x over previous
#include <cuda_runtime.h>
#include <cuda_bf16.h>
#include <math.h>
#include <limits.h>
#include <stdint.h>

#define NNODES 16384
#define NGRAPH 256
#define NODES_PER_G 64
#define HEADS 8
#define FDIM 64
#define HF 512
#define MAXE 262144

// ---------------- scratch (device globals; no allocations allowed) -------------
__device__ float g_xl[NNODES * HF];
__device__ float g_xr[NNODES * HF];
__device__ float g_go[NNODES * HF];
__device__ __nv_bfloat16 g_A2[(size_t)NNODES * 1024];  // [Ahi | Alo]  (2K, K<=512)
__device__ __nv_bfloat16 g_B2[(size_t)1024 * 1024];    // [Bhi | Blo]  (N-major)
__device__ int g_deg[NNODES];
__device__ int g_off[NNODES + 1];
__device__ int g_cur[NNODES];
__device__ int g_csr[MAXE];

// ---------------- helpers --------------------------------------------------------
__device__ __forceinline__ uint32_t smem_u32(const void* p) {
    uint32_t a;
    asm("{ .reg .u64 t; cvta.to.shared.u64 t, %1; cvt.u32.u64 %0, t; }" : "=r"(a) : "l"(p));
    return a;
}
__device__ __forceinline__ void cp16(void* dst, const void* src) {
    uint32_t d = smem_u32(dst);
    asm volatile("cp.async.cg.shared.global [%0], [%1], 16;" :: "r"(d), "l"(src));
}
__device__ __forceinline__ void ldsm4(uint32_t& r0, uint32_t& r1, uint32_t& r2,
                                      uint32_t& r3, uint32_t addr) {
    asm volatile("ldmatrix.sync.aligned.m8n8.x4.shared.b16 {%0,%1,%2,%3}, [%4];"
                 : "=r"(r0), "=r"(r1), "=r"(r2), "=r"(r3) : "r"(addr));
}
__device__ __forceinline__ void mma16816(float* c, uint32_t a0, uint32_t a1,
                                         uint32_t a2, uint32_t a3,
                                         uint32_t b0, uint32_t b1) {
    asm volatile(
        "mma.sync.aligned.m16n8k16.row.col.f32.bf16.bf16.f32 "
        "{%0,%1,%2,%3}, {%4,%5,%6,%7}, {%8,%9}, {%0,%1,%2,%3};"
        : "+f"(c[0]), "+f"(c[1]), "+f"(c[2]), "+f"(c[3])
        : "r"(a0), "r"(a1), "r"(a2), "r"(a3), "r"(b0), "r"(b1));
}

// ---------------- CSR build (graph topology; once per launch) --------------------
__global__ void hist_kernel(const int* __restrict__ dst, int E, int* __restrict__ deg) {
    int i = blockIdx.x * 256 + threadIdx.x;
    if (i < E) atomicAdd(&deg[dst[i]], 1);
}

__global__ __launch_bounds__(1024) void scan_kernel(const int* __restrict__ deg,
                                                    int* __restrict__ off,
                                                    int* __restrict__ cur) {
    __shared__ int sa[1024], sb[1024];
    int t = threadIdx.x;
    int base = t * 16;
    int local[16];
    int s = 0;
#pragma unroll
    for (int i = 0; i < 16; i++) { local[i] = s; s += deg[base + i]; }
    sa[t] = s;
    __syncthreads();
    int* pin = sa; int* pout = sb;
#pragma unroll
    for (int step = 1; step < 1024; step <<= 1) {
        int v = pin[t] + ((t >= step) ? pin[t - step] : 0);
        __syncthreads();
        pout[t] = v;
        __syncthreads();
        int* tmp = pin; pin = pout; pout = tmp;
    }
    int inc = pin[t];
    int exc = inc - s;
#pragma unroll
    for (int i = 0; i < 16; i++) {
        int o = exc + local[i];
        off[base + i] = o;
        cur[base + i] = o;
    }
    if (t == 1023) off[NNODES] = inc;
}

__global__ void scatter_kernel(const int* __restrict__ src, const int* __restrict__ dst,
                               int E, int* __restrict__ cur, int* __restrict__ csr) {
    int i = blockIdx.x * 256 + threadIdx.x;
    if (i >= E) return;
    int pos = atomicAdd(&cur[dst[i]], 1);
    csr[pos] = src[i];
}

// ---------------- weight prep: B2[n][hi|lo] from Wl/Wr --------------------------
__global__ void prep_w_kernel(const float* __restrict__ Wl,
                              const float* __restrict__ Wr,
                              __nv_bfloat16* __restrict__ B2, int K) {
    __shared__ float t[32][33];
    int k0 = blockIdx.x * 32, n0 = blockIdx.y * 32;
    int tx = threadIdx.x, ty = threadIdx.y;
    const float* W = (n0 < 512) ? Wl : Wr;
    int nn0 = n0 & 511;
    for (int i = ty; i < 32; i += 8)
        t[i][tx] = W[(size_t)(k0 + i) * 512 + nn0 + tx];
    __syncthreads();
    int K2 = 2 * K;
    for (int i = ty; i < 32; i += 8) {
        float v = t[tx][i];
        __nv_bfloat16 h = __float2bfloat16(v);
        __nv_bfloat16 l = __float2bfloat16(v - __bfloat162float(h));
        size_t base = (size_t)(n0 + i) * K2 + k0 + tx;
        B2[base]     = h;   // seg0: hi
        B2[base + K] = l;   // seg1: lo
    }
}

// ---------------- activation prep (layer 1 input only) --------------------------
__global__ void prep_a_kernel(const float* __restrict__ A,
                              __nv_bfloat16* __restrict__ A2, int K) {
    int i = blockIdx.x * 256 + threadIdx.x;
    if (i >= NNODES * K) return;
    int n = i / K, k = i - n * K;
    float v = A[i];
    __nv_bfloat16 h = __float2bfloat16(v);
    __nv_bfloat16 l = __float2bfloat16(v - __bfloat162float(h));
    size_t base = (size_t)n * (2 * K) + k;
    A2[base]     = h;   // hi
    A2[base + K] = l;   // lo
}

// ---------------- mma.sync bf16 GEMM with hi/lo dedup ---------------------------
// xl columns (n0<512):  C = Ahi*Bhi + Ahi*Blo + Alo*Bhi   (full 3-term, ~2^-16)
// xr columns (n0>=512): C = Ahi*Bhi + Ahi*Blo             (2-term, ~2^-9; feeds
//                       only attention logits -> alpha err ~8e-4, final ~2e-4)
// CTA tile 128x128, 8 warps (2M x 4N) of 64x32 (m16n8k16), BK=32,
// 3-stage cp.async, 2 CTAs/SM.
#define BKB 32
#define LDS_AB 40                    // 32 + 8 skew
#define NST 3
#define ST_T (128 * LDS_AB)          // elems per tile per stage
#define GEMM_SMEM (NST * 3 * ST_T * 2)   // 92160 bytes

__global__ __launch_bounds__(256, 2)
void gemm_bf16_kernel(const __nv_bfloat16* __restrict__ A2,
                      const __nv_bfloat16* __restrict__ B2,
                      float* __restrict__ Cl, float* __restrict__ Cr, int K)
{
    extern __shared__ __nv_bfloat16 sm[];
    __nv_bfloat16* As = sm;                     // [NST][128][40]
    __nv_bfloat16* Bh = sm + NST * ST_T;        // [NST][128][40]
    __nv_bfloat16* Bl = sm + 2 * NST * ST_T;    // [NST][128][40]

    const int tid = threadIdx.x;
    const int wid = tid >> 5;
    const int lane = tid & 31;
    const int m0 = blockIdx.y * 128;
    const int n0 = blockIdx.x * 128;
    const int wm = wid & 1;        // 64-row slab
    const int wn = wid >> 1;       // 0..3, 32-col slab
    const int K2 = 2 * K;

    const __nv_bfloat16* Ab = A2 + (size_t)m0 * K2;
    const __nv_bfloat16* Bb = B2 + (size_t)n0 * K2;

    const int row = tid >> 1;
    const int c0 = (tid & 1) * 16;

    // ldmatrix lane geometry (verified)
    const int aRow = wm * 64 + (lane & 15);
    const int aCol = (lane >> 4) * 8;
    const int bRow = (lane & 7) + (lane >> 4) * 8;
    const int bCol = ((lane >> 3) & 1) * 8;

    const uint32_t sAs = smem_u32(As);
    const uint32_t sBh = smem_u32(Bh);
    const uint32_t sBl = smem_u32(Bl);

    float c[4][4][4];
#pragma unroll
    for (int g = 0; g < 4; g++)
#pragma unroll
        for (int h = 0; h < 4; h++)
#pragma unroll
            for (int r = 0; r < 4; r++) c[g][h][r] = 0.f;

    const int nk = K >> 5;   // chunks per pass

    // ================= LOOP 1: Ahi x (Bhi, Blo) =================
#pragma unroll
    for (int st = 0; st < NST - 1; st++) {
        const int k0 = st * BKB;
        __nv_bfloat16* as = As + st * ST_T + row * LDS_AB + c0;
        const __nv_bfloat16* ag = Ab + (size_t)row * K2 + k0 + c0;
        cp16(as, ag); cp16(as + 8, ag + 8);
        __nv_bfloat16* bh = Bh + st * ST_T + row * LDS_AB + c0;
        const __nv_bfloat16* bgh = Bb + (size_t)row * K2 + k0 + c0;
        cp16(bh, bgh); cp16(bh + 8, bgh + 8);
        __nv_bfloat16* bl = Bl + st * ST_T + row * LDS_AB + c0;
        const __nv_bfloat16* bgl = bgh + K;
        cp16(bl, bgl); cp16(bl + 8, bgl + 8);
        asm volatile("cp.async.commit_group;");
    }

    for (int kt = 0; kt < nk; kt++) {
        const int buf = kt % NST;
        asm volatile("cp.async.wait_group %0;" :: "n"(NST - 2));
        __syncthreads();

        const uint32_t aBase = sAs + (buf * ST_T) * 2;
        const uint32_t hBase = sBh + (buf * ST_T) * 2;
        const uint32_t lBase = sBl + (buf * ST_T) * 2;
#pragma unroll
        for (int ks = 0; ks < 2; ks++) {
            uint32_t a[4][4];
#pragma unroll
            for (int g = 0; g < 4; g++)
                ldsm4(a[g][0], a[g][1], a[g][2], a[g][3],
                      aBase + ((aRow + g * 16) * LDS_AB + ks * 16 + aCol) * 2);
            uint32_t bh[4][2], bl[4][2];
#pragma unroll
            for (int h2 = 0; h2 < 2; h2++) {
                ldsm4(bh[h2 * 2][0], bh[h2 * 2][1], bh[h2 * 2 + 1][0], bh[h2 * 2 + 1][1],
                      hBase + ((wn * 32 + h2 * 16 + bRow) * LDS_AB + ks * 16 + bCol) * 2);
                ldsm4(bl[h2 * 2][0], bl[h2 * 2][1], bl[h2 * 2 + 1][0], bl[h2 * 2 + 1][1],
                      lBase + ((wn * 32 + h2 * 16 + bRow) * LDS_AB + ks * 16 + bCol) * 2);
            }
#pragma unroll
            for (int g = 0; g < 4; g++)
#pragma unroll
                for (int h = 0; h < 4; h++) {
                    mma16816(c[g][h], a[g][0], a[g][1], a[g][2], a[g][3],
                             bh[h][0], bh[h][1]);
                    mma16816(c[g][h], a[g][0], a[g][1], a[g][2], a[g][3],
                             bl[h][0], bl[h][1]);
                }
        }

        const int knext = kt + NST - 1;
        if (knext < nk) {
            const int st = knext % NST;
            const int k0 = knext * BKB;
            __nv_bfloat16* as = As + st * ST_T + row * LDS_AB + c0;
            const __nv_bfloat16* ag = Ab + (size_t)row * K2 + k0 + c0;
            cp16(as, ag); cp16(as + 8, ag + 8);
            __nv_bfloat16* bh2 = Bh + st * ST_T + row * LDS_AB + c0;
            const __nv_bfloat16* bgh = Bb + (size_t)row * K2 + k0 + c0;
            cp16(bh2, bgh); cp16(bh2 + 8, bgh + 8);
            __nv_bfloat16* bl2 = Bl + st * ST_T + row * LDS_AB + c0;
            const __nv_bfloat16* bgl = bgh + K;
            cp16(bl2, bgl); cp16(bl2 + 8, bgl + 8);
        }
        asm volatile("cp.async.commit_group;");
    }

    // drain pipeline before reusing smem
    asm volatile("cp.async.wait_group 0;");
    __syncthreads();

    // ================= LOOP 2: Alo x Bhi (xl columns only) =================
    if (n0 < 512) {
#pragma unroll
        for (int st = 0; st < NST - 1; st++) {
            const int k0 = st * BKB;
            __nv_bfloat16* as = As + st * ST_T + row * LDS_AB + c0;
            const __nv_bfloat16* ag = Ab + (size_t)row * K2 + K + k0 + c0;   // A lo
            cp16(as, ag); cp16(as + 8, ag + 8);
            __nv_bfloat16* bh = Bh + st * ST_T + row * LDS_AB + c0;
            const __nv_bfloat16* bgh = Bb + (size_t)row * K2 + k0 + c0;      // B hi
            cp16(bh, bgh); cp16(bh + 8, bgh + 8);
            asm volatile("cp.async.commit_group;");
        }

        for (int kt = 0; kt < nk; kt++) {
            const int buf = kt % NST;
            asm volatile("cp.async.wait_group %0;" :: "n"(NST - 2));
            __syncthreads();

            const uint32_t aBase = sAs + (buf * ST_T) * 2;
            const uint32_t hBase = sBh + (buf * ST_T) * 2;
#pragma unroll
            for (int ks = 0; ks < 2; ks++) {
                uint32_t a[4][4];
#pragma unroll
                for (int g = 0; g < 4; g++)
                    ldsm4(a[g][0], a[g][1], a[g][2], a[g][3],
                          aBase + ((aRow + g * 16) * LDS_AB + ks * 16 + aCol) * 2);
                uint32_t bh[4][2];
#pragma unroll
                for (int h2 = 0; h2 < 2; h2++)
                    ldsm4(bh[h2 * 2][0], bh[h2 * 2][1], bh[h2 * 2 + 1][0], bh[h2 * 2 + 1][1],
                          hBase + ((wn * 32 + h2 * 16 + bRow) * LDS_AB + ks * 16 + bCol) * 2);
#pragma unroll
                for (int g = 0; g < 4; g++)
#pragma unroll
                    for (int h = 0; h < 4; h++)
                        mma16816(c[g][h], a[g][0], a[g][1], a[g][2], a[g][3],
                                 bh[h][0], bh[h][1]);
            }

            const int knext = kt + NST - 1;
            if (knext < nk) {
                const int st = knext % NST;
                const int k0 = knext * BKB;
                __nv_bfloat16* as = As + st * ST_T + row * LDS_AB + c0;
                const __nv_bfloat16* ag = Ab + (size_t)row * K2 + K + k0 + c0;
                cp16(as, ag); cp16(as + 8, ag + 8);
                __nv_bfloat16* bh2 = Bh + st * ST_T + row * LDS_AB + c0;
                const __nv_bfloat16* bgh = Bb + (size_t)row * K2 + k0 + c0;
                cp16(bh2, bgh); cp16(bh2 + 8, bgh + 8);
            }
            asm volatile("cp.async.commit_group;");
        }
        asm volatile("cp.async.wait_group 0;");
    }

    // epilogue
    float* Cbase = (n0 < 512) ? Cl : Cr;
    const int ncol = n0 & 511;
    const int crow = m0 + wm * 64 + (lane >> 2);
    const int ccol = ncol + wn * 32 + (lane & 3) * 2;
#pragma unroll
    for (int g = 0; g < 4; g++) {
#pragma unroll
        for (int h = 0; h < 4; h++) {
            float* p0 = Cbase + (size_t)(crow + g * 16) * HF + ccol + h * 8;
            *(float2*)p0 = make_float2(c[g][h][0], c[g][h][1]);
            float* p1 = p0 + 8 * HF;
            *(float2*)p1 = make_float2(c[g][h][2], c[g][h][3]);
        }
    }
}

// ---------------- fused CSR GAT (dual-edge unrolled), no atomics ----------------
__device__ __forceinline__ float warp_logit_reduce(float r) {
    r += __shfl_xor_sync(0xffffffffu, r, 8);
    r += __shfl_xor_sync(0xffffffffu, r, 4);
    r += __shfl_xor_sync(0xffffffffu, r, 2);
    r += __shfl_xor_sync(0xffffffffu, r, 1);
    return r;
}
__device__ __forceinline__ float leaky_dot(float4 a, float4 b, float4 t) {
    float mx = a.x + b.x, my = a.y + b.y, mz = a.z + b.z, mw = a.w + b.w;
    mx = mx > 0.f ? mx : 0.2f * mx;
    my = my > 0.f ? my : 0.2f * my;
    mz = mz > 0.f ? mz : 0.2f * mz;
    mw = mw > 0.f ? mw : 0.2f * mw;
    return mx * t.x + my * t.y + mz * t.z + mw * t.w;
}

__global__ __launch_bounds__(256) void gat_csr_concat_kernel(
    const int* __restrict__ off, const int* __restrict__ csr,
    const float* __restrict__ xl, const float* __restrict__ xr,
    const float* __restrict__ att, float* __restrict__ out)
{
    int d = blockIdx.x * 8 + (threadIdx.x >> 5);
    int lane = threadIdx.x & 31;
    const float4* at4 = (const float4*)att;
    const float4* pxr = (const float4*)(xr + (size_t)d * HF);
    float4 t[4], b[4], acc[4];
    float den[4];
#pragma unroll
    for (int it = 0; it < 4; it++) {
        t[it] = at4[it * 32 + lane];
        b[it] = pxr[it * 32 + lane];
        acc[it] = make_float4(0.f, 0.f, 0.f, 0.f);
        den[it] = 0.f;
    }
    int e0 = off[d], e1 = off[d + 1];
    int j = e0;
    for (; j + 1 < e1; j += 2) {
        int s0 = csr[j], s1 = csr[j + 1];
        const float4* p0 = (const float4*)(xl + (size_t)s0 * HF);
        const float4* p1 = (const float4*)(xl + (size_t)s1 * HF);
#pragma unroll
        for (int it = 0; it < 4; it++) {
            float4 a0 = p0[it * 32 + lane];
            float4 a1 = p1[it * 32 + lane];
            float r0 = warp_logit_reduce(leaky_dot(a0, b[it], t[it]));
            float r1 = warp_logit_reduce(leaky_dot(a1, b[it], t[it]));
            float pp0 = expf(r0);     // shift-free softmax (logits O(1))
            float pp1 = expf(r1);
            den[it] += pp0 + pp1;
            acc[it].x += pp0 * a0.x + pp1 * a1.x;
            acc[it].y += pp0 * a0.y + pp1 * a1.y;
            acc[it].z += pp0 * a0.z + pp1 * a1.z;
            acc[it].w += pp0 * a0.w + pp1 * a1.w;
        }
    }
    if (j < e1) {
        int s0 = csr[j];
        const float4* p0 = (const float4*)(xl + (size_t)s0 * HF);
#pragma unroll
        for (int it = 0; it < 4; it++) {
            float4 a0 = p0[it * 32 + lane];
            float r0 = warp_logit_reduce(leaky_dot(a0, b[it], t[it]));
            float pp0 = expf(r0);
            den[it] += pp0;
            acc[it].x += pp0 * a0.x; acc[it].y += pp0 * a0.y;
            acc[it].z += pp0 * a0.z; acc[it].w += pp0 * a0.w;
        }
    }
    float4* po = (float4*)(out + (size_t)d * HF);
#pragma unroll
    for (int it = 0; it < 4; it++) {
        float inv = 1.0f / (den[it] + 1e-16f);
        po[it * 32 + lane] = make_float4(acc[it].x * inv, acc[it].y * inv,
                                         acc[it].z * inv, acc[it].w * inv);
    }
}

__global__ __launch_bounds__(256) void gat_csr_mean_kernel(
    const int* __restrict__ off, const int* __restrict__ csr,
    const float* __restrict__ xl, const float* __restrict__ xr,
    const float* __restrict__ att, float* __restrict__ out)
{
    int d = blockIdx.x * 8 + (threadIdx.x >> 5);
    int lane = threadIdx.x & 31;
    const float4* at4 = (const float4*)att;
    const float4* pxr = (const float4*)(xr + (size_t)d * HF);
    float4 t[4], b[4], acc[4];
    float den[4];
#pragma unroll
    for (int it = 0; it < 4; it++) {
        t[it] = at4[it * 32 + lane];
        b[it] = pxr[it * 32 + lane];
        acc[it] = make_float4(0.f, 0.f, 0.f, 0.f);
        den[it] = 0.f;
    }
    int e0 = off[d], e1 = off[d + 1];
    int j = e0;
    for (; j + 1 < e1; j += 2) {
        int s0 = csr[j], s1 = csr[j + 1];
        const float4* p0 = (const float4*)(xl + (size_t)s0 * HF);
        const float4* p1 = (const float4*)(xl + (size_t)s1 * HF);
#pragma unroll
        for (int it = 0; it < 4; it++) {
            float4 a0 = p0[it * 32 + lane];
            float4 a1 = p1[it * 32 + lane];
            float r0 = warp_logit_reduce(leaky_dot(a0, b[it], t[it]));
            float r1 = warp_logit_reduce(leaky_dot(a1, b[it], t[it]));
            float pp0 = expf(r0);
            float pp1 = expf(r1);
            den[it] += pp0 + pp1;
            acc[it].x += pp0 * a0.x + pp1 * a1.x;
            acc[it].y += pp0 * a0.y + pp1 * a1.y;
            acc[it].z += pp0 * a0.z + pp1 * a1.z;
            acc[it].w += pp0 * a0.w + pp1 * a1.w;
        }
    }
    if (j < e1) {
        int s0 = csr[j];
        const float4* p0 = (const float4*)(xl + (size_t)s0 * HF);
#pragma unroll
        for (int it = 0; it < 4; it++) {
            float4 a0 = p0[it * 32 + lane];
            float r0 = warp_logit_reduce(leaky_dot(a0, b[it], t[it]));
            float pp0 = expf(r0);
            den[it] += pp0;
            acc[it].x += pp0 * a0.x; acc[it].y += pp0 * a0.y;
            acc[it].z += pp0 * a0.z; acc[it].w += pp0 * a0.w;
        }
    }
#pragma unroll
    for (int it = 0; it < 4; it++) {
        float inv = 1.0f / (den[it] + 1e-16f);
        acc[it].x *= inv; acc[it].y *= inv; acc[it].z *= inv; acc[it].w *= inv;
        acc[it].x += __shfl_xor_sync(0xffffffffu, acc[it].x, 16);
        acc[it].y += __shfl_xor_sync(0xffffffffu, acc[it].y, 16);
        acc[it].z += __shfl_xor_sync(0xffffffffu, acc[it].z, 16);
        acc[it].w += __shfl_xor_sync(0xffffffffu, acc[it].w, 16);
    }
    float4 tot;
    tot.x = (acc[0].x + acc[1].x + acc[2].x + acc[3].x) * 0.125f;
    tot.y = (acc[0].y + acc[1].y + acc[2].y + acc[3].y) * 0.125f;
    tot.z = (acc[0].z + acc[1].z + acc[2].z + acc[3].z) * 0.125f;
    tot.w = (acc[0].w + acc[1].w + acc[2].w + acc[3].w) * 0.125f;
    if (lane < 16)
        ((float4*)(out + (size_t)d * FDIM))[lane] = tot;
}

// ---------------- GraphNorm + bias + ReLU -> bf16 hi/lo split (layers 1,2) ------
__global__ __launch_bounds__(512) void graphnorm_relu_split_kernel(
    const float* __restrict__ gin, const float* __restrict__ bias,
    const float* __restrict__ w, const float* __restrict__ bb,
    const float* __restrict__ ms, __nv_bfloat16* __restrict__ A2)
{
    const int D = HF;              // 512
    int g = blockIdx.x;
    int c = threadIdx.x;
    const float* base = gin + (size_t)g * NODES_PER_G * D;
    float bc = bias[c];
    float s = 0.f;
#pragma unroll 8
    for (int i = 0; i < NODES_PER_G; i++) s += base[(size_t)i * D + c];
    float mean = (s + (float)NODES_PER_G * bc) * (1.0f / NODES_PER_G);
    float msm = ms[c] * mean;
    float var = 0.f;
#pragma unroll 8
    for (int i = 0; i < NODES_PER_G; i++) {
        float xc = base[(size_t)i * D + c] + bc - msm;
        var += xc * xc;
    }
    var *= (1.0f / NODES_PER_G);
    float inv = rsqrtf(var + 1e-5f);
    float wc = w[c], b2 = bb[c];
#pragma unroll 8
    for (int i = 0; i < NODES_PER_G; i++) {
        float xc = base[(size_t)i * D + c] + bc - msm;
        float y = wc * xc * inv + b2;
        y = y > 0.f ? y : 0.f;
        __nv_bfloat16 h = __float2bfloat16(y);
        __nv_bfloat16 l = __float2bfloat16(y - __bfloat162float(h));
        size_t a0 = (size_t)(g * NODES_PER_G + i) * 1024 + c;
        A2[a0]       = h;   // hi
        A2[a0 + 512] = l;   // lo
    }
}

// ---------------- GraphNorm L3 + ReLU + mean pool + linear head (fused) ---------
__global__ __launch_bounds__(64) void graphnorm_pool_linear_kernel(
    const float* __restrict__ gin, const float* __restrict__ bias,
    const float* __restrict__ w, const float* __restrict__ bb,
    const float* __restrict__ ms,
    const float* __restrict__ Wlin, const float* __restrict__ blin,
    float* __restrict__ out)
{
    const int D = FDIM;            // 64
    int g = blockIdx.x;
    int c = threadIdx.x;
    const float* base = gin + (size_t)g * NODES_PER_G * D;
    float bc = bias[c];
    float s = 0.f;
#pragma unroll 8
    for (int i = 0; i < NODES_PER_G; i++) s += base[(size_t)i * D + c];
    float mean = (s + (float)NODES_PER_G * bc) * (1.0f / NODES_PER_G);
    float msm = ms[c] * mean;
    float var = 0.f;
#pragma unroll 8
    for (int i = 0; i < NODES_PER_G; i++) {
        float xc = base[(size_t)i * D + c] + bc - msm;
        var += xc * xc;
    }
    var *= (1.0f / NODES_PER_G);
    float inv = rsqrtf(var + 1e-5f);
    float wc = w[c], b2 = bb[c];
    float psum = 0.f;
#pragma unroll 8
    for (int i = 0; i < NODES_PER_G; i++) {
        float xc = base[(size_t)i * D + c] + bc - msm;
        float y = wc * xc * inv + b2;
        psum += (y > 0.f ? y : 0.f);
    }
    __shared__ float pooled[FDIM];
    pooled[c] = psum * (1.0f / NODES_PER_G);
    __syncthreads();
    if (c < 2) {
        float acc = blin[c];
#pragma unroll
        for (int k = 0; k < FDIM; k++) acc += pooled[k] * Wlin[k * 2 + c];
        out[g * 2 + c] = acc;
    }
}

// ---------------- host side ------------------------------------------------------
extern "C" void kernel_launch(void* const* d_in, const int* in_sizes, int n_in,
                              void* d_out, int out_size)
{
    const float* x   = (const float*)d_in[0];
    const int*   src = (const int*)d_in[1];
    const int*   dst = (const int*)d_in[2];
    int E = in_sizes[1];

    const float* Wl1 = (const float*)d_in[4];
    const float* Wr1 = (const float*)d_in[5];
    const float* att1= (const float*)d_in[6];
    const float* b1  = (const float*)d_in[7];
    const float* gw1 = (const float*)d_in[8];
    const float* gb1 = (const float*)d_in[9];
    const float* gm1 = (const float*)d_in[10];

    const float* Wl2 = (const float*)d_in[11];
    const float* Wr2 = (const float*)d_in[12];
    const float* att2= (const float*)d_in[13];
    const float* b2  = (const float*)d_in[14];
    const float* gw2 = (const float*)d_in[15];
    const float* gb2 = (const float*)d_in[16];
    const float* gm2 = (const float*)d_in[17];

    const float* Wl3 = (const float*)d_in[18];
    const float* Wr3 = (const float*)d_in[19];
    const float* att3= (const float*)d_in[20];
    const float* b3  = (const float*)d_in[21];
    const float* gw3 = (const float*)d_in[22];
    const float* gb3 = (const float*)d_in[23];
    const float* gm3 = (const float*)d_in[24];

    const float* Wlin = (const float*)d_in[25];
    const float* blin = (const float*)d_in[26];

    float* out = (float*)d_out;

    cudaFuncSetAttribute(gemm_bf16_kernel,
                         cudaFuncAttributeMaxDynamicSharedMemorySize, GEMM_SMEM);

    float *xl, *xr, *go;
    __nv_bfloat16 *A2, *B2;
    int *deg, *off, *cur, *csr;
    cudaGetSymbolAddress((void**)&xl,  g_xl);
    cudaGetSymbolAddress((void**)&xr,  g_xr);
    cudaGetSymbolAddress((void**)&go,  g_go);
    cudaGetSymbolAddress((void**)&A2,  g_A2);
    cudaGetSymbolAddress((void**)&B2,  g_B2);
    cudaGetSymbolAddress((void**)&deg, g_deg);
    cudaGetSymbolAddress((void**)&off, g_off);
    cudaGetSymbolAddress((void**)&cur, g_cur);
    cudaGetSymbolAddress((void**)&csr, g_csr);

    // CSR build (once; shared by all 3 layers)
    cudaMemsetAsync(deg, 0, NNODES * sizeof(int));
    hist_kernel<<<(E + 255) / 256, 256>>>(dst, E, deg);
    scan_kernel<<<1, 1024>>>(deg, off, cur);
    scatter_kernel<<<(E + 255) / 256, 256>>>(src, dst, E, cur, csr);

    // ---- layer 1 (K=256) ----
    prep_a_kernel<<<(NNODES * 256 + 255) / 256, 256>>>(x, A2, 256);
    prep_w_kernel<<<dim3(8, 32), dim3(32, 8)>>>(Wl1, Wr1, B2, 256);
    gemm_bf16_kernel<<<dim3(8, 128), 256, GEMM_SMEM>>>(A2, B2, xl, xr, 256);
    gat_csr_concat_kernel<<<NNODES / 8, 256>>>(off, csr, xl, xr, att1, go);
    graphnorm_relu_split_kernel<<<NGRAPH, HF>>>(go, b1, gw1, gb1, gm1, A2);

    // ---- layer 2 (K=512) ----
    prep_w_kernel<<<dim3(16, 32), dim3(32, 8)>>>(Wl2, Wr2, B2, 512);
    gemm_bf16_kernel<<<dim3(8, 128), 256, GEMM_SMEM>>>(A2, B2, xl, xr, 512);
    gat_csr_concat_kernel<<<NNODES / 8, 256>>>(off, csr, xl, xr, att2, go);
    graphnorm_relu_split_kernel<<<NGRAPH, HF>>>(go, b2, gw2, gb2, gm2, A2);

    // ---- layer 3 (K=512, mean heads) + fused norm/pool/linear ----
    prep_w_kernel<<<dim3(16, 32), dim3(32, 8)>>>(Wl3, Wr3, B2, 512);
    gemm_bf16_kernel<<<dim3(8, 128), 256, GEMM_SMEM>>>(A2, B2, xl, xr, 512);
    gat_csr_mean_kernel<<<NNODES / 8, 256>>>(off, csr, xl, xr, att3, go);
    graphnorm_pool_linear_kernel<<<NGRAPH, FDIM>>>(go, b3, gw3, gb3, gm3,
                                                   Wlin, blin, out);
}

// round 16
// speedup vs baseline: 1.1677x; 1.0518x over previous
#include <cuda_runtime.h>
#include <cuda_bf16.h>
#include <math.h>
#include <limits.h>
#include <stdint.h>

#define NNODES 16384
#define NGRAPH 256
#define NODES_PER_G 64
#define HEADS 8
#define FDIM 64
#define HF 512
#define MAXE 262144

// ---------------- scratch (device globals; no allocations allowed) -------------
__device__ float g_xl[NNODES * HF];
__device__ float g_xr[NNODES * HF];
__device__ float g_go[NNODES * HF];
__device__ __nv_bfloat16 g_A2[(size_t)NNODES * 1024];  // [Ahi | Alo]  (2K, K<=512)
__device__ __nv_bfloat16 g_B2[(size_t)1024 * 1024];    // [Bhi | Blo]  (N-major)
__device__ int g_deg[NNODES];
__device__ int g_off[NNODES + 1];
__device__ int g_cur[NNODES];
__device__ int g_csr[MAXE];

// ---------------- helpers --------------------------------------------------------
__device__ __forceinline__ uint32_t smem_u32(const void* p) {
    uint32_t a;
    asm("{ .reg .u64 t; cvta.to.shared.u64 t, %1; cvt.u32.u64 %0, t; }" : "=r"(a) : "l"(p));
    return a;
}
__device__ __forceinline__ void cp16(void* dst, const void* src) {
    uint32_t d = smem_u32(dst);
    asm volatile("cp.async.cg.shared.global [%0], [%1], 16;" :: "r"(d), "l"(src));
}
__device__ __forceinline__ void ldsm4(uint32_t& r0, uint32_t& r1, uint32_t& r2,
                                      uint32_t& r3, uint32_t addr) {
    asm volatile("ldmatrix.sync.aligned.m8n8.x4.shared.b16 {%0,%1,%2,%3}, [%4];"
                 : "=r"(r0), "=r"(r1), "=r"(r2), "=r"(r3) : "r"(addr));
}
__device__ __forceinline__ void mma16816(float* c, uint32_t a0, uint32_t a1,
                                         uint32_t a2, uint32_t a3,
                                         uint32_t b0, uint32_t b1) {
    asm volatile(
        "mma.sync.aligned.m16n8k16.row.col.f32.bf16.bf16.f32 "
        "{%0,%1,%2,%3}, {%4,%5,%6,%7}, {%8,%9}, {%0,%1,%2,%3};"
        : "+f"(c[0]), "+f"(c[1]), "+f"(c[2]), "+f"(c[3])
        : "r"(a0), "r"(a1), "r"(a2), "r"(a3), "r"(b0), "r"(b1));
}

// ---------------- CSR build (graph topology; once per launch) --------------------
__global__ void hist_kernel(const int* __restrict__ dst, int E, int* __restrict__ deg) {
    int i = blockIdx.x * 256 + threadIdx.x;
    if (i < E) atomicAdd(&deg[dst[i]], 1);
}

__global__ __launch_bounds__(1024) void scan_kernel(const int* __restrict__ deg,
                                                    int* __restrict__ off,
                                                    int* __restrict__ cur) {
    __shared__ int sa[1024], sb[1024];
    int t = threadIdx.x;
    int base = t * 16;
    int local[16];
    int s = 0;
#pragma unroll
    for (int i = 0; i < 16; i++) { local[i] = s; s += deg[base + i]; }
    sa[t] = s;
    __syncthreads();
    int* pin = sa; int* pout = sb;
#pragma unroll
    for (int step = 1; step < 1024; step <<= 1) {
        int v = pin[t] + ((t >= step) ? pin[t - step] : 0);
        __syncthreads();
        pout[t] = v;
        __syncthreads();
        int* tmp = pin; pin = pout; pout = tmp;
    }
    int inc = pin[t];
    int exc = inc - s;
#pragma unroll
    for (int i = 0; i < 16; i++) {
        int o = exc + local[i];
        off[base + i] = o;
        cur[base + i] = o;
    }
    if (t == 1023) off[NNODES] = inc;
}

__global__ void scatter_kernel(const int* __restrict__ src, const int* __restrict__ dst,
                               int E, int* __restrict__ cur, int* __restrict__ csr) {
    int i = blockIdx.x * 256 + threadIdx.x;
    if (i >= E) return;
    int pos = atomicAdd(&cur[dst[i]], 1);
    csr[pos] = src[i];
}

// ---------------- weight prep: B2[n][hi|lo] from Wl/Wr --------------------------
__global__ void prep_w_kernel(const float* __restrict__ Wl,
                              const float* __restrict__ Wr,
                              __nv_bfloat16* __restrict__ B2, int K) {
    __shared__ float t[32][33];
    int k0 = blockIdx.x * 32, n0 = blockIdx.y * 32;
    int tx = threadIdx.x, ty = threadIdx.y;
    const float* W = (n0 < 512) ? Wl : Wr;
    int nn0 = n0 & 511;
    for (int i = ty; i < 32; i += 8)
        t[i][tx] = W[(size_t)(k0 + i) * 512 + nn0 + tx];
    __syncthreads();
    int K2 = 2 * K;
    for (int i = ty; i < 32; i += 8) {
        float v = t[tx][i];
        __nv_bfloat16 h = __float2bfloat16(v);
        __nv_bfloat16 l = __float2bfloat16(v - __bfloat162float(h));
        size_t base = (size_t)(n0 + i) * K2 + k0 + tx;
        B2[base]     = h;   // seg0: hi
        B2[base + K] = l;   // seg1: lo
    }
}

// ---------------- activation prep (layer 1 input only) --------------------------
__global__ void prep_a_kernel(const float* __restrict__ A,
                              __nv_bfloat16* __restrict__ A2, int K) {
    int i = blockIdx.x * 256 + threadIdx.x;
    if (i >= NNODES * K) return;
    int n = i / K, k = i - n * K;
    float v = A[i];
    __nv_bfloat16 h = __float2bfloat16(v);
    __nv_bfloat16 l = __float2bfloat16(v - __bfloat162float(h));
    size_t base = (size_t)n * (2 * K) + k;
    A2[base]     = h;   // hi
    A2[base + K] = l;   // lo
}

// ---------------- mma.sync bf16 GEMM with asymmetric precision ------------------
// xl columns (n0<512):  C = Ahi*Bhi + Ahi*Blo + Alo*Bhi  (3-term, ~2^-16)
// xr columns (n0>=512): C = Ahi*Bhi                      (1-term, ~2^-8; feeds
//   only attention logits; measured propagation: 2-term gave final 8e-5, so
//   1-term predicts ~1.6e-4 — inside the 1e-3 gate with 6x margin)
// CTA tile 128x128, 8 warps (2M x 4N) of 64x32 (m16n8k16), BK=32,
// 3-stage cp.async, 2 CTAs/SM.
#define BKB 32
#define LDS_AB 40                    // 32 + 8 skew
#define NST 3
#define ST_T (128 * LDS_AB)          // elems per tile per stage
#define GEMM_SMEM (NST * 3 * ST_T * 2)   // 92160 bytes

__global__ __launch_bounds__(256, 2)
void gemm_bf16_kernel(const __nv_bfloat16* __restrict__ A2,
                      const __nv_bfloat16* __restrict__ B2,
                      float* __restrict__ Cl, float* __restrict__ Cr, int K)
{
    extern __shared__ __nv_bfloat16 sm[];
    __nv_bfloat16* As = sm;                     // [NST][128][40]
    __nv_bfloat16* Bh = sm + NST * ST_T;        // [NST][128][40]
    __nv_bfloat16* Bl = sm + 2 * NST * ST_T;    // [NST][128][40]

    const int tid = threadIdx.x;
    const int wid = tid >> 5;
    const int lane = tid & 31;
    const int m0 = blockIdx.y * 128;
    const int n0 = blockIdx.x * 128;
    const int wm = wid & 1;        // 64-row slab
    const int wn = wid >> 1;       // 0..3, 32-col slab
    const int K2 = 2 * K;
    const bool full = (n0 < 512);  // xl: 3-term; xr: 1-term

    const __nv_bfloat16* Ab = A2 + (size_t)m0 * K2;
    const __nv_bfloat16* Bb = B2 + (size_t)n0 * K2;

    const int row = tid >> 1;
    const int c0 = (tid & 1) * 16;

    // ldmatrix lane geometry (verified)
    const int aRow = wm * 64 + (lane & 15);
    const int aCol = (lane >> 4) * 8;
    const int bRow = (lane & 7) + (lane >> 4) * 8;
    const int bCol = ((lane >> 3) & 1) * 8;

    const uint32_t sAs = smem_u32(As);
    const uint32_t sBh = smem_u32(Bh);
    const uint32_t sBl = smem_u32(Bl);

    float c[4][4][4];
#pragma unroll
    for (int g = 0; g < 4; g++)
#pragma unroll
        for (int h = 0; h < 4; h++)
#pragma unroll
            for (int r = 0; r < 4; r++) c[g][h][r] = 0.f;

    const int nk = K >> 5;   // chunks per pass

    // ================= LOOP 1: Ahi x Bhi (+ Ahi x Blo if full) =================
#pragma unroll
    for (int st = 0; st < NST - 1; st++) {
        const int k0 = st * BKB;
        __nv_bfloat16* as = As + st * ST_T + row * LDS_AB + c0;
        const __nv_bfloat16* ag = Ab + (size_t)row * K2 + k0 + c0;
        cp16(as, ag); cp16(as + 8, ag + 8);
        __nv_bfloat16* bh = Bh + st * ST_T + row * LDS_AB + c0;
        const __nv_bfloat16* bgh = Bb + (size_t)row * K2 + k0 + c0;
        cp16(bh, bgh); cp16(bh + 8, bgh + 8);
        if (full) {
            __nv_bfloat16* bl = Bl + st * ST_T + row * LDS_AB + c0;
            const __nv_bfloat16* bgl = bgh + K;
            cp16(bl, bgl); cp16(bl + 8, bgl + 8);
        }
        asm volatile("cp.async.commit_group;");
    }

    for (int kt = 0; kt < nk; kt++) {
        const int buf = kt % NST;
        asm volatile("cp.async.wait_group %0;" :: "n"(NST - 2));
        __syncthreads();

        const uint32_t aBase = sAs + (buf * ST_T) * 2;
        const uint32_t hBase = sBh + (buf * ST_T) * 2;
        const uint32_t lBase = sBl + (buf * ST_T) * 2;
#pragma unroll
        for (int ks = 0; ks < 2; ks++) {
            uint32_t a[4][4];
#pragma unroll
            for (int g = 0; g < 4; g++)
                ldsm4(a[g][0], a[g][1], a[g][2], a[g][3],
                      aBase + ((aRow + g * 16) * LDS_AB + ks * 16 + aCol) * 2);
            uint32_t bh[4][2];
#pragma unroll
            for (int h2 = 0; h2 < 2; h2++)
                ldsm4(bh[h2 * 2][0], bh[h2 * 2][1], bh[h2 * 2 + 1][0], bh[h2 * 2 + 1][1],
                      hBase + ((wn * 32 + h2 * 16 + bRow) * LDS_AB + ks * 16 + bCol) * 2);
#pragma unroll
            for (int g = 0; g < 4; g++)
#pragma unroll
                for (int h = 0; h < 4; h++)
                    mma16816(c[g][h], a[g][0], a[g][1], a[g][2], a[g][3],
                             bh[h][0], bh[h][1]);
            if (full) {
                uint32_t bl[4][2];
#pragma unroll
                for (int h2 = 0; h2 < 2; h2++)
                    ldsm4(bl[h2 * 2][0], bl[h2 * 2][1], bl[h2 * 2 + 1][0], bl[h2 * 2 + 1][1],
                          lBase + ((wn * 32 + h2 * 16 + bRow) * LDS_AB + ks * 16 + bCol) * 2);
#pragma unroll
                for (int g = 0; g < 4; g++)
#pragma unroll
                    for (int h = 0; h < 4; h++)
                        mma16816(c[g][h], a[g][0], a[g][1], a[g][2], a[g][3],
                                 bl[h][0], bl[h][1]);
            }
        }

        const int knext = kt + NST - 1;
        if (knext < nk) {
            const int st = knext % NST;
            const int k0 = knext * BKB;
            __nv_bfloat16* as = As + st * ST_T + row * LDS_AB + c0;
            const __nv_bfloat16* ag = Ab + (size_t)row * K2 + k0 + c0;
            cp16(as, ag); cp16(as + 8, ag + 8);
            __nv_bfloat16* bh2 = Bh + st * ST_T + row * LDS_AB + c0;
            const __nv_bfloat16* bgh = Bb + (size_t)row * K2 + k0 + c0;
            cp16(bh2, bgh); cp16(bh2 + 8, bgh + 8);
            if (full) {
                __nv_bfloat16* bl2 = Bl + st * ST_T + row * LDS_AB + c0;
                const __nv_bfloat16* bgl = bgh + K;
                cp16(bl2, bgl); cp16(bl2 + 8, bgl + 8);
            }
        }
        asm volatile("cp.async.commit_group;");
    }

    // drain pipeline before reusing smem
    asm volatile("cp.async.wait_group 0;");
    __syncthreads();

    // ================= LOOP 2: Alo x Bhi (xl columns only) =================
    if (full) {
#pragma unroll
        for (int st = 0; st < NST - 1; st++) {
            const int k0 = st * BKB;
            __nv_bfloat16* as = As + st * ST_T + row * LDS_AB + c0;
            const __nv_bfloat16* ag = Ab + (size_t)row * K2 + K + k0 + c0;   // A lo
            cp16(as, ag); cp16(as + 8, ag + 8);
            __nv_bfloat16* bh = Bh + st * ST_T + row * LDS_AB + c0;
            const __nv_bfloat16* bgh = Bb + (size_t)row * K2 + k0 + c0;      // B hi
            cp16(bh, bgh); cp16(bh + 8, bgh + 8);
            asm volatile("cp.async.commit_group;");
        }

        for (int kt = 0; kt < nk; kt++) {
            const int buf = kt % NST;
            asm volatile("cp.async.wait_group %0;" :: "n"(NST - 2));
            __syncthreads();

            const uint32_t aBase = sAs + (buf * ST_T) * 2;
            const uint32_t hBase = sBh + (buf * ST_T) * 2;
#pragma unroll
            for (int ks = 0; ks < 2; ks++) {
                uint32_t a[4][4];
#pragma unroll
                for (int g = 0; g < 4; g++)
                    ldsm4(a[g][0], a[g][1], a[g][2], a[g][3],
                          aBase + ((aRow + g * 16) * LDS_AB + ks * 16 + aCol) * 2);
                uint32_t bh[4][2];
#pragma unroll
                for (int h2 = 0; h2 < 2; h2++)
                    ldsm4(bh[h2 * 2][0], bh[h2 * 2][1], bh[h2 * 2 + 1][0], bh[h2 * 2 + 1][1],
                          hBase + ((wn * 32 + h2 * 16 + bRow) * LDS_AB + ks * 16 + bCol) * 2);
#pragma unroll
                for (int g = 0; g < 4; g++)
#pragma unroll
                    for (int h = 0; h < 4; h++)
                        mma16816(c[g][h], a[g][0], a[g][1], a[g][2], a[g][3],
                                 bh[h][0], bh[h][1]);
            }

            const int knext = kt + NST - 1;
            if (knext < nk) {
                const int st = knext % NST;
                const int k0 = knext * BKB;
                __nv_bfloat16* as = As + st * ST_T + row * LDS_AB + c0;
                const __nv_bfloat16* ag = Ab + (size_t)row * K2 + K + k0 + c0;
                cp16(as, ag); cp16(as + 8, ag + 8);
                __nv_bfloat16* bh2 = Bh + st * ST_T + row * LDS_AB + c0;
                const __nv_bfloat16* bgh = Bb + (size_t)row * K2 + k0 + c0;
                cp16(bh2, bgh); cp16(bh2 + 8, bgh + 8);
            }
            asm volatile("cp.async.commit_group;");
        }
        asm volatile("cp.async.wait_group 0;");
    }

    // epilogue
    float* Cbase = full ? Cl : Cr;
    const int ncol = n0 & 511;
    const int crow = m0 + wm * 64 + (lane >> 2);
    const int ccol = ncol + wn * 32 + (lane & 3) * 2;
#pragma unroll
    for (int g = 0; g < 4; g++) {
#pragma unroll
        for (int h = 0; h < 4; h++) {
            float* p0 = Cbase + (size_t)(crow + g * 16) * HF + ccol + h * 8;
            *(float2*)p0 = make_float2(c[g][h][0], c[g][h][1]);
            float* p1 = p0 + 8 * HF;
            *(float2*)p1 = make_float2(c[g][h][2], c[g][h][3]);
        }
    }
}

// ---------------- fused CSR GAT (dual-edge unrolled), no atomics ----------------
__device__ __forceinline__ float warp_logit_reduce(float r) {
    r += __shfl_xor_sync(0xffffffffu, r, 8);
    r += __shfl_xor_sync(0xffffffffu, r, 4);
    r += __shfl_xor_sync(0xffffffffu, r, 2);
    r += __shfl_xor_sync(0xffffffffu, r, 1);
    return r;
}
__device__ __forceinline__ float leaky_dot(float4 a, float4 b, float4 t) {
    float mx = a.x + b.x, my = a.y + b.y, mz = a.z + b.z, mw = a.w + b.w;
    mx = mx > 0.f ? mx : 0.2f * mx;
    my = my > 0.f ? my : 0.2f * my;
    mz = mz > 0.f ? mz : 0.2f * mz;
    mw = mw > 0.f ? mw : 0.2f * mw;
    return mx * t.x + my * t.y + mz * t.z + mw * t.w;
}

__global__ __launch_bounds__(256) void gat_csr_concat_kernel(
    const int* __restrict__ off, const int* __restrict__ csr,
    const float* __restrict__ xl, const float* __restrict__ xr,
    const float* __restrict__ att, float* __restrict__ out)
{
    int d = blockIdx.x * 8 + (threadIdx.x >> 5);
    int lane = threadIdx.x & 31;
    const float4* at4 = (const float4*)att;
    const float4* pxr = (const float4*)(xr + (size_t)d * HF);
    float4 t[4], b[4], acc[4];
    float den[4];
#pragma unroll
    for (int it = 0; it < 4; it++) {
        t[it] = at4[it * 32 + lane];
        b[it] = pxr[it * 32 + lane];
        acc[it] = make_float4(0.f, 0.f, 0.f, 0.f);
        den[it] = 0.f;
    }
    int e0 = off[d], e1 = off[d + 1];
    int j = e0;
    for (; j + 1 < e1; j += 2) {
        int s0 = csr[j], s1 = csr[j + 1];
        const float4* p0 = (const float4*)(xl + (size_t)s0 * HF);
        const float4* p1 = (const float4*)(xl + (size_t)s1 * HF);
#pragma unroll
        for (int it = 0; it < 4; it++) {
            float4 a0 = p0[it * 32 + lane];
            float4 a1 = p1[it * 32 + lane];
            float r0 = warp_logit_reduce(leaky_dot(a0, b[it], t[it]));
            float r1 = warp_logit_reduce(leaky_dot(a1, b[it], t[it]));
            float pp0 = expf(r0);     // shift-free softmax (logits O(1))
            float pp1 = expf(r1);
            den[it] += pp0 + pp1;
            acc[it].x += pp0 * a0.x + pp1 * a1.x;
            acc[it].y += pp0 * a0.y + pp1 * a1.y;
            acc[it].z += pp0 * a0.z + pp1 * a1.z;
            acc[it].w += pp0 * a0.w + pp1 * a1.w;
        }
    }
    if (j < e1) {
        int s0 = csr[j];
        const float4* p0 = (const float4*)(xl + (size_t)s0 * HF);
#pragma unroll
        for (int it = 0; it < 4; it++) {
            float4 a0 = p0[it * 32 + lane];
            float r0 = warp_logit_reduce(leaky_dot(a0, b[it], t[it]));
            float pp0 = expf(r0);
            den[it] += pp0;
            acc[it].x += pp0 * a0.x; acc[it].y += pp0 * a0.y;
            acc[it].z += pp0 * a0.z; acc[it].w += pp0 * a0.w;
        }
    }
    float4* po = (float4*)(out + (size_t)d * HF);
#pragma unroll
    for (int it = 0; it < 4; it++) {
        float inv = 1.0f / (den[it] + 1e-16f);
        po[it * 32 + lane] = make_float4(acc[it].x * inv, acc[it].y * inv,
                                         acc[it].z * inv, acc[it].w * inv);
    }
}

__global__ __launch_bounds__(256) void gat_csr_mean_kernel(
    const int* __restrict__ off, const int* __restrict__ csr,
    const float* __restrict__ xl, const float* __restrict__ xr,
    const float* __restrict__ att, float* __restrict__ out)
{
    int d = blockIdx.x * 8 + (threadIdx.x >> 5);
    int lane = threadIdx.x & 31;
    const float4* at4 = (const float4*)att;
    const float4* pxr = (const float4*)(xr + (size_t)d * HF);
    float4 t[4], b[4], acc[4];
    float den[4];
#pragma unroll
    for (int it = 0; it < 4; it++) {
        t[it] = at4[it * 32 + lane];
        b[it] = pxr[it * 32 + lane];
        acc[it] = make_float4(0.f, 0.f, 0.f, 0.f);
        den[it] = 0.f;
    }
    int e0 = off[d], e1 = off[d + 1];
    int j = e0;
    for (; j + 1 < e1; j += 2) {
        int s0 = csr[j], s1 = csr[j + 1];
        const float4* p0 = (const float4*)(xl + (size_t)s0 * HF);
        const float4* p1 = (const float4*)(xl + (size_t)s1 * HF);
#pragma unroll
        for (int it = 0; it < 4; it++) {
            float4 a0 = p0[it * 32 + lane];
            float4 a1 = p1[it * 32 + lane];
            float r0 = warp_logit_reduce(leaky_dot(a0, b[it], t[it]));
            float r1 = warp_logit_reduce(leaky_dot(a1, b[it], t[it]));
            float pp0 = expf(r0);
            float pp1 = expf(r1);
            den[it] += pp0 + pp1;
            acc[it].x += pp0 * a0.x + pp1 * a1.x;
            acc[it].y += pp0 * a0.y + pp1 * a1.y;
            acc[it].z += pp0 * a0.z + pp1 * a1.z;
            acc[it].w += pp0 * a0.w + pp1 * a1.w;
        }
    }
    if (j < e1) {
        int s0 = csr[j];
        const float4* p0 = (const float4*)(xl + (size_t)s0 * HF);
#pragma unroll
        for (int it = 0; it < 4; it++) {
            float4 a0 = p0[it * 32 + lane];
            float r0 = warp_logit_reduce(leaky_dot(a0, b[it], t[it]));
            float pp0 = expf(r0);
            den[it] += pp0;
            acc[it].x += pp0 * a0.x; acc[it].y += pp0 * a0.y;
            acc[it].z += pp0 * a0.z; acc[it].w += pp0 * a0.w;
        }
    }
#pragma unroll
    for (int it = 0; it < 4; it++) {
        float inv = 1.0f / (den[it] + 1e-16f);
        acc[it].x *= inv; acc[it].y *= inv; acc[it].z *= inv; acc[it].w *= inv;
        acc[it].x += __shfl_xor_sync(0xffffffffu, acc[it].x, 16);
        acc[it].y += __shfl_xor_sync(0xffffffffu, acc[it].y, 16);
        acc[it].z += __shfl_xor_sync(0xffffffffu, acc[it].z, 16);
        acc[it].w += __shfl_xor_sync(0xffffffffu, acc[it].w, 16);
    }
    float4 tot;
    tot.x = (acc[0].x + acc[1].x + acc[2].x + acc[3].x) * 0.125f;
    tot.y = (acc[0].y + acc[1].y + acc[2].y + acc[3].y) * 0.125f;
    tot.z = (acc[0].z + acc[1].z + acc[2].z + acc[3].z) * 0.125f;
    tot.w = (acc[0].w + acc[1].w + acc[2].w + acc[3].w) * 0.125f;
    if (lane < 16)
        ((float4*)(out + (size_t)d * FDIM))[lane] = tot;
}

// ---------------- GraphNorm + bias + ReLU -> bf16 hi/lo split (layers 1,2) ------
__global__ __launch_bounds__(512) void graphnorm_relu_split_kernel(
    const float* __restrict__ gin, const float* __restrict__ bias,
    const float* __restrict__ w, const float* __restrict__ bb,
    const float* __restrict__ ms, __nv_bfloat16* __restrict__ A2)
{
    const int D = HF;              // 512
    int g = blockIdx.x;
    int c = threadIdx.x;
    const float* base = gin + (size_t)g * NODES_PER_G * D;
    float bc = bias[c];
    float s = 0.f;
#pragma unroll 8
    for (int i = 0; i < NODES_PER_G; i++) s += base[(size_t)i * D + c];
    float mean = (s + (float)NODES_PER_G * bc) * (1.0f / NODES_PER_G);
    float msm = ms[c] * mean;
    float var = 0.f;
#pragma unroll 8
    for (int i = 0; i < NODES_PER_G; i++) {
        float xc = base[(size_t)i * D + c] + bc - msm;
        var += xc * xc;
    }
    var *= (1.0f / NODES_PER_G);
    float inv = rsqrtf(var + 1e-5f);
    float wc = w[c], b2 = bb[c];
#pragma unroll 8
    for (int i = 0; i < NODES_PER_G; i++) {
        float xc = base[(size_t)i * D + c] + bc - msm;
        float y = wc * xc * inv + b2;
        y = y > 0.f ? y : 0.f;
        __nv_bfloat16 h = __float2bfloat16(y);
        __nv_bfloat16 l = __float2bfloat16(y - __bfloat162float(h));
        size_t a0 = (size_t)(g * NODES_PER_G + i) * 1024 + c;
        A2[a0]       = h;   // hi
        A2[a0 + 512] = l;   // lo
    }
}

// ---------------- GraphNorm L3 + ReLU + mean pool + linear head (fused) ---------
__global__ __launch_bounds__(64) void graphnorm_pool_linear_kernel(
    const float* __restrict__ gin, const float* __restrict__ bias,
    const float* __restrict__ w, const float* __restrict__ bb,
    const float* __restrict__ ms,
    const float* __restrict__ Wlin, const float* __restrict__ blin,
    float* __restrict__ out)
{
    const int D = FDIM;            // 64
    int g = blockIdx.x;
    int c = threadIdx.x;
    const float* base = gin + (size_t)g * NODES_PER_G * D;
    float bc = bias[c];
    float s = 0.f;
#pragma unroll 8
    for (int i = 0; i < NODES_PER_G; i++) s += base[(size_t)i * D + c];
    float mean = (s + (float)NODES_PER_G * bc) * (1.0f / NODES_PER_G);
    float msm = ms[c] * mean;
    float var = 0.f;
#pragma unroll 8
    for (int i = 0; i < NODES_PER_G; i++) {
        float xc = base[(size_t)i * D + c] + bc - msm;
        var += xc * xc;
    }
    var *= (1.0f / NODES_PER_G);
    float inv = rsqrtf(var + 1e-5f);
    float wc = w[c], b2 = bb[c];
    float psum = 0.f;
#pragma unroll 8
    for (int i = 0; i < NODES_PER_G; i++) {
        float xc = base[(size_t)i * D + c] + bc - msm;
        float y = wc * xc * inv + b2;
        psum += (y > 0.f ? y : 0.f);
    }
    __shared__ float pooled[FDIM];
    pooled[c] = psum * (1.0f / NODES_PER_G);
    __syncthreads();
    if (c < 2) {
        float acc = blin[c];
#pragma unroll
        for (int k = 0; k < FDIM; k++) acc += pooled[k] * Wlin[k * 2 + c];
        out[g * 2 + c] = acc;
    }
}

// ---------------- host side ------------------------------------------------------
extern "C" void kernel_launch(void* const* d_in, const int* in_sizes, int n_in,
                              void* d_out, int out_size)
{
    const float* x   = (const float*)d_in[0];
    const int*   src = (const int*)d_in[1];
    const int*   dst = (const int*)d_in[2];
    int E = in_sizes[1];

    const float* Wl1 = (const float*)d_in[4];
    const float* Wr1 = (const float*)d_in[5];
    const float* att1= (const float*)d_in[6];
    const float* b1  = (const float*)d_in[7];
    const float* gw1 = (const float*)d_in[8];
    const float* gb1 = (const float*)d_in[9];
    const float* gm1 = (const float*)d_in[10];

    const float* Wl2 = (const float*)d_in[11];
    const float* Wr2 = (const float*)d_in[12];
    const float* att2= (const float*)d_in[13];
    const float* b2  = (const float*)d_in[14];
    const float* gw2 = (const float*)d_in[15];
    const float* gb2 = (const float*)d_in[16];
    const float* gm2 = (const float*)d_in[17];

    const float* Wl3 = (const float*)d_in[18];
    const float* Wr3 = (const float*)d_in[19];
    const float* att3= (const float*)d_in[20];
    const float* b3  = (const float*)d_in[21];
    const float* gw3 = (const float*)d_in[22];
    const float* gb3 = (const float*)d_in[23];
    const float* gm3 = (const float*)d_in[24];

    const float* Wlin = (const float*)d_in[25];
    const float* blin = (const float*)d_in[26];

    float* out = (float*)d_out;

    cudaFuncSetAttribute(gemm_bf16_kernel,
                         cudaFuncAttributeMaxDynamicSharedMemorySize, GEMM_SMEM);

    float *xl, *xr, *go;
    __nv_bfloat16 *A2, *B2;
    int *deg, *off, *cur, *csr;
    cudaGetSymbolAddress((void**)&xl,  g_xl);
    cudaGetSymbolAddress((void**)&xr,  g_xr);
    cudaGetSymbolAddress((void**)&go,  g_go);
    cudaGetSymbolAddress((void**)&A2,  g_A2);
    cudaGetSymbolAddress((void**)&B2,  g_B2);
    cudaGetSymbolAddress((void**)&deg, g_deg);
    cudaGetSymbolAddress((void**)&off, g_off);
    cudaGetSymbolAddress((void**)&cur, g_cur);
    cudaGetSymbolAddress((void**)&csr, g_csr);

    // CSR build (once; shared by all 3 layers)
    cudaMemsetAsync(deg, 0, NNODES * sizeof(int));
    hist_kernel<<<(E + 255) / 256, 256>>>(dst, E, deg);
    scan_kernel<<<1, 1024>>>(deg, off, cur);
    scatter_kernel<<<(E + 255) / 256, 256>>>(src, dst, E, cur, csr);

    // ---- layer 1 (K=256) ----
    prep_a_kernel<<<(NNODES * 256 + 255) / 256, 256>>>(x, A2, 256);
    prep_w_kernel<<<dim3(8, 32), dim3(32, 8)>>>(Wl1, Wr1, B2, 256);
    gemm_bf16_kernel<<<dim3(8, 128), 256, GEMM_SMEM>>>(A2, B2, xl, xr, 256);
    gat_csr_concat_kernel<<<NNODES / 8, 256>>>(off, csr, xl, xr, att1, go);
    graphnorm_relu_split_kernel<<<NGRAPH, HF>>>(go, b1, gw1, gb1, gm1, A2);

    // ---- layer 2 (K=512) ----
    prep_w_kernel<<<dim3(16, 32), dim3(32, 8)>>>(Wl2, Wr2, B2, 512);
    gemm_bf16_kernel<<<dim3(8, 128), 256, GEMM_SMEM>>>(A2, B2, xl, xr, 512);
    gat_csr_concat_kernel<<<NNODES / 8, 256>>>(off, csr, xl, xr, att2, go);
    graphnorm_relu_split_kernel<<<NGRAPH, HF>>>(go, b2, gw2, gb2, gm2, A2);

    // ---- layer 3 (K=512, mean heads) + fused norm/pool/linear ----
    prep_w_kernel<<<dim3(16, 32), dim3(32, 8)>>>(Wl3, Wr3, B2, 512);
    gemm_bf16_kernel<<<dim3(8, 128), 256, GEMM_SMEM>>>(A2, B2, xl, xr, 512);
    gat_csr_mean_kernel<<<NNODES / 8, 256>>>(off, csr, xl, xr, att3, go);
    graphnorm_pool_linear_kernel<<<NGRAPH, FDIM>>>(go, b3, gw3, gb3, gm3,
                                                   Wlin, blin, out);
}